// round 13
// baseline (speedup 1.0000x reference)
#include <cuda_runtime.h>
#include <cuda_bf16.h>
#include <math.h>
#include <stdint.h>

// ---------------- problem constants ----------------
#define Bv 16
#define Sv 3136
#define Ev 768
#define Hv 16
#define Dv 48
#define NTOK (Bv * Sv)      // 50176
#define LDK 4608            // bytes per packed row, K=768 triplet (2304 bf16)
#define LDKU 1152           // u32 per packed row (K=768 triplet)
#define LDH 6272            // bytes per plain-bf16 row, K=3136
#define LDHU 1568           // u32 per plain row
#define NSTG 3
#define STG_BYTES 32768
#define GEMM_SMEM (NSTG * STG_BYTES)   // 98304

// ---------------- scratch (device globals) ----------------
__device__ uint32_t g_x2[(size_t)(NTOK + 128) * LDKU]; // packed x rows (A triplet)
__device__ uint32_t g_xtH[(size_t)Bv * Ev * LDHU];     // X^T hi, plain bf16
__device__ uint32_t g_xtL[(size_t)Bv * Ev * LDHU];     // X^T lo, plain bf16
__device__ float    g_R1[(size_t)Bv * Ev * Ev];        // H^T H (upper tiles)
__device__ float    g_R2[(size_t)Bv * Ev * Ev];        // H^T L (full)
__device__ uint32_t g_Cp[(size_t)Bv * Ev * LDKU];      // C packed (A triplet)
__device__ float    g_V2[(size_t)Bv * Ev * 1536];      // C @ [Wq|Wk]
__device__ uint32_t g_wt1[(size_t)1536 * LDKU];        // [Wq|Wk]^T packed (B)
__device__ uint32_t g_wv2[(size_t)Ev * LDKU];          // Wv rows packed (B layout)
__device__ uint32_t g_Pt2[(size_t)Bv * Ev * LDKU];     // P_b^T packed (A layout)
__device__ uint32_t g_wbT[(size_t)Bv * Ev * LDKU];     // W_b^T packed (B layout)

// ---------------- helpers ----------------
__device__ __forceinline__ uint32_t s2u(const void* p) {
    uint32_t a;
    asm("{ .reg .u64 t; cvta.to.shared.u64 t, %1; cvt.u32.u64 %0, t; }"
        : "=r"(a) : "l"(p));
    return a;
}
#define SWZ(o) ((o) ^ (((o) >> 3) & 0x70))

__device__ __forceinline__ void cpasync16(uint32_t s, const void* g) {
    asm volatile("cp.async.cg.shared.global [%0], [%1], 16;\n" :: "r"(s), "l"(g));
}
__device__ __forceinline__ void cp_commit() {
    asm volatile("cp.async.commit_group;\n");
}
template <int N> __device__ __forceinline__ void cp_wait() {
    asm volatile("cp.async.wait_group %0;\n" :: "n"(N));
}
__device__ __forceinline__ void ldm4(uint32_t& r0, uint32_t& r1, uint32_t& r2,
                                     uint32_t& r3, uint32_t a) {
    asm volatile("ldmatrix.sync.aligned.m8n8.x4.shared.b16 {%0,%1,%2,%3}, [%4];"
                 : "=r"(r0), "=r"(r1), "=r"(r2), "=r"(r3) : "r"(a));
}
__device__ __forceinline__ void mma16816(float* d, const uint32_t* a,
                                         const uint32_t* b) {
    asm volatile(
        "mma.sync.aligned.m16n8k16.row.col.f32.bf16.bf16.f32 "
        "{%0,%1,%2,%3}, {%4,%5,%6,%7}, {%8,%9}, {%0,%1,%2,%3};"
        : "+f"(d[0]), "+f"(d[1]), "+f"(d[2]), "+f"(d[3])
        : "r"(a[0]), "r"(a[1]), "r"(a[2]), "r"(a[3]), "r"(b[0]), "r"(b[1]));
}
__device__ __forceinline__ void split2(float x, uint32_t& h, uint32_t& l) {
    __nv_bfloat16 hb = __float2bfloat16(x);
    float rem = x - __bfloat162float(hb);
    __nv_bfloat16 lb = __float2bfloat16(rem);
    h = (uint32_t)__bfloat16_as_ushort(hb);
    l = (uint32_t)__bfloat16_as_ushort(lb);
}

// ---------------------------------------------------------------------------
// bf16 mma.sync GEMM (proven config). Extensions:
//  tri>0 : merged launch — blockIdx.x < tri does triangular tiles on (A,B)->C,
//          blockIdx.x >= tri does rectangular tiles on (A,Balt)->Calt (NT=6).
//  packC : epilogue writes B-layout bf16 triplets into (uint32_t*)C.
// ---------------------------------------------------------------------------
__global__ __launch_bounds__(256, 2) void gemm_mma(
    const char* __restrict__ A, const char* __restrict__ B,
    float* __restrict__ C, const float* __restrict__ bias, int N, int NT,
    size_t aStride, size_t bStride, size_t cStride, int Mrows,
    int kRowBytes, int nkch, int tri,
    const char* __restrict__ Balt, float* __restrict__ Calt, int packC)
{
    extern __shared__ char sm[];
    const int tid  = threadIdx.x;
    const int wid  = tid >> 5, lane = tid & 31;
    const int wm   = wid & 3;
    const int wn   = wid >> 2;
    const int bat  = blockIdx.y;
    int bm, bn;
    const char* Bsel = B;
    float* Csel = C;
    if (tri > 0) {
        if ((int)blockIdx.x < tri) {
            int t = blockIdx.x, r = 0, rl = 6;
            while (t >= rl) { t -= rl; rl--; r++; }
            bm = r; bn = r + t;
        } else {
            int t = blockIdx.x - tri;
            bm = t / 6; bn = t % 6;
            Bsel = Balt; Csel = Calt;
        }
    } else {
        bm = blockIdx.x / NT; bn = blockIdx.x % NT;
    }
    const uint32_t smb = s2u(sm);

    const char* Ab = A + (size_t)bat * aStride + (size_t)bm * 128 * kRowBytes;
    const char* Bb = Bsel + (size_t)bat * bStride + (size_t)bn * 128 * kRowBytes;

    const int ldr = tid >> 1;
    const int ldc = (tid & 1) * 64;

    auto loadch = [&](int sp, int ck) {
        uint32_t sa = smb + sp * STG_BYTES;
        uint32_t sb = sa + 16384;
        const char* a0 = Ab + ck * 128;
        const char* b0 = Bb + ck * 128;
        #pragma unroll
        for (int i = 0; i < 4; i++) {
            int cb = ldc + i * 16;
            cpasync16(sa + SWZ(ldr * 128 + cb), a0 + (size_t)ldr * kRowBytes + cb);
            cpasync16(sb + SWZ(ldr * 128 + cb), b0 + (size_t)ldr * kRowBytes + cb);
        }
        cp_commit();
    };

    float acc[2][8][4];
    #pragma unroll
    for (int m = 0; m < 2; m++)
        #pragma unroll
        for (int n = 0; n < 8; n++)
            #pragma unroll
            for (int p = 0; p < 4; p++) acc[m][n][p] = 0.f;

    loadch(0, 0);
    loadch(1, 1);

    const int a_row = (lane & 7) + ((lane >> 3) & 1) * 8;
    const int a_cb  = (lane >> 4) * 16;
    const int b_row = (lane & 7) + (lane >> 4) * 8;
    const int b_cb  = ((lane >> 3) & 1) * 16;

    uint32_t af[2][2][4], bf[2][8][2];

    auto ldfrag = [&](uint32_t sa, uint32_t sb, int ks, int buf) {
        #pragma unroll
        for (int mb = 0; mb < 2; mb++) {
            int r = wm * 32 + mb * 16 + a_row;
            ldm4(af[buf][mb][0], af[buf][mb][1], af[buf][mb][2], af[buf][mb][3],
                 sa + SWZ(r * 128 + ks * 32 + a_cb));
        }
        #pragma unroll
        for (int nb2 = 0; nb2 < 4; nb2++) {
            int r = wn * 64 + nb2 * 16 + b_row;
            ldm4(bf[buf][2 * nb2][0], bf[buf][2 * nb2][1],
                 bf[buf][2 * nb2 + 1][0], bf[buf][2 * nb2 + 1][1],
                 sb + SWZ(r * 128 + ks * 32 + b_cb));
        }
    };

    for (int k = 0; k < nkch; k++) {
        cp_wait<1>();
        __syncthreads();

        int kp = k + 2;
        if (kp < nkch) loadch(kp % NSTG, kp);
        else cp_commit();

        uint32_t sa = smb + (k % NSTG) * STG_BYTES;
        uint32_t sb = sa + 16384;

        ldfrag(sa, sb, 0, 0);
        #pragma unroll
        for (int ks = 0; ks < 4; ks++) {
            int c = ks & 1;
            if (ks < 3) ldfrag(sa, sb, ks + 1, c ^ 1);
            #pragma unroll
            for (int mb = 0; mb < 2; mb++)
                #pragma unroll
                for (int nb = 0; nb < 8; nb++)
                    mma16816(acc[mb][nb], af[c][mb], bf[c][nb]);
        }
    }

    const int er = lane >> 2;
    const int ec = (lane & 3) * 2;
    const int rbase = bm * 128 + wm * 32;

    if (packC) {
        uint32_t* Cpk = (uint32_t*)Csel + (size_t)bat * cStride;
        #pragma unroll
        for (int mb = 0; mb < 2; mb++) {
            int r0 = rbase + mb * 16 + er;
            #pragma unroll
            for (int nb = 0; nb < 8; nb++) {
                int col = bn * 128 + wn * 64 + nb * 8 + ec;   // even
                uint32_t h0, l0, h1, l1;
                split2(acc[mb][nb][0], h0, l0);
                split2(acc[mb][nb][1], h1, l1);
                uint32_t* o = Cpk + (size_t)r0 * LDKU + 3 * (col >> 1);
                o[0] = h0 | (l0 << 16);
                o[1] = h0 | (h1 << 16);
                o[2] = l1 | (h1 << 16);
                split2(acc[mb][nb][2], h0, l0);
                split2(acc[mb][nb][3], h1, l1);
                uint32_t* o2 = Cpk + (size_t)(r0 + 8) * LDKU + 3 * (col >> 1);
                o2[0] = h0 | (l0 << 16);
                o2[1] = h0 | (h1 << 16);
                o2[2] = l1 | (h1 << 16);
            }
        }
        return;
    }

    float* Cb = Csel + (size_t)bat * cStride
                + (size_t)rbase * N + (size_t)bn * 128 + wn * 64;
    float bvs[8][2];
    #pragma unroll
    for (int nb = 0; nb < 8; nb++) {
        if (bias) {
            const float* bp = bias + (size_t)bn * 128 + wn * 64 + nb * 8 + ec;
            bvs[nb][0] = bp[0]; bvs[nb][1] = bp[1];
        } else { bvs[nb][0] = 0.f; bvs[nb][1] = 0.f; }
    }
    #pragma unroll
    for (int mb = 0; mb < 2; mb++) {
        int r0 = rbase + mb * 16 + er;
        bool w0 = r0 < Mrows, w1 = (r0 + 8) < Mrows;
        #pragma unroll
        for (int nb = 0; nb < 8; nb++) {
            int col = nb * 8 + ec;
            float2 v0 = {acc[mb][nb][0] + bvs[nb][0], acc[mb][nb][1] + bvs[nb][1]};
            float2 v1 = {acc[mb][nb][2] + bvs[nb][0], acc[mb][nb][3] + bvs[nb][1]};
            if (w0) *(float2*)(Cb + (size_t)(mb * 16 + er) * N + col) = v0;
            if (w1) *(float2*)(Cb + (size_t)(mb * 16 + er + 8) * N + col) = v1;
        }
    }
}

// ---------------------------------------------------------------------------
// Fused X packing: x2 (row-major A-triplet), xtH, xtL (transposed hi/lo).
// grid = (12 e-tiles, 49 s-tiles, 16 b).
// ---------------------------------------------------------------------------
__global__ __launch_bounds__(256) void pack_x(
    const float* __restrict__ x, uint32_t* __restrict__ x2,
    uint32_t* __restrict__ xtH, uint32_t* __restrict__ xtL)
{
    __shared__ float ts[64][65];
    const int e0 = blockIdx.x * 64, s0 = blockIdx.y * 64, b = blockIdx.z;
    const int tid = threadIdx.x;
    #pragma unroll
    for (int i = 0; i < 16; i++) {
        int idx = tid + i * 256;
        int sl = idx >> 6, el = idx & 63;
        ts[sl][el] = x[((size_t)b * Sv + s0 + sl) * Ev + e0 + el];
    }
    __syncthreads();
    #pragma unroll
    for (int i = 0; i < 8; i++) {
        int item = tid + i * 256;
        int el = item >> 5, sp = item & 31;
        float v0 = ts[2 * sp][el], v1 = ts[2 * sp + 1][el];
        uint32_t h0, l0, h1, l1;
        split2(v0, h0, l0);
        split2(v1, h1, l1);
        size_t r = ((size_t)b * Ev + e0 + el) * LDHU + (s0 >> 1) + sp;
        xtH[r] = h0 | (h1 << 16);
        xtL[r] = l0 | (l1 << 16);
    }
    #pragma unroll
    for (int i = 0; i < 8; i++) {
        int item = tid + i * 256;
        int sl = item >> 5, pe = item & 31;
        float v0 = ts[sl][2 * pe], v1 = ts[sl][2 * pe + 1];
        uint32_t h0, l0, h1, l1;
        split2(v0, h0, l0);
        split2(v1, h1, l1);
        size_t o = ((size_t)b * Sv + s0 + sl) * LDKU + 3 * ((e0 >> 1) + pe);
        x2[o + 0] = h0 | (h0 << 16);
        x2[o + 1] = l0 | (h1 << 16);
        x2[o + 2] = h1 | (l1 << 16);
    }
}

// ---------------------------------------------------------------------------
// Merged weight packing: job A = [Wq|Wk]^T B-triplet (1536*384 items),
// job B = Wv rows B-triplet (768*384 items).
// ---------------------------------------------------------------------------
__global__ void pack_w(const float* __restrict__ Wqkv,
                       uint32_t* __restrict__ wt1, uint32_t* __restrict__ wv2)
{
    int t = blockIdx.x * 256 + threadIdx.x;
    const int NW = 1536 * 384;
    if (t < NW) {
        int n = t / 384, kp = t % 384;
        float x0 = Wqkv[(size_t)(2 * kp) * 2304 + n];
        float x1 = Wqkv[(size_t)(2 * kp + 1) * 2304 + n];
        uint32_t h0, l0, h1, l1;
        split2(x0, h0, l0);
        split2(x1, h1, l1);
        uint32_t* o = wt1 + (size_t)n * LDKU + 3 * kp;
        o[0] = h0 | (l0 << 16);
        o[1] = h0 | (h1 << 16);
        o[2] = l1 | (h1 << 16);
    } else {
        int t2 = t - NW;
        if (t2 >= Ev * 384) return;
        int e = t2 / 384, c = t2 % 384;
        float x0 = Wqkv[(size_t)e * 2304 + 1536 + 2 * c];
        float x1 = Wqkv[(size_t)e * 2304 + 1536 + 2 * c + 1];
        uint32_t h0, l0, h1, l1;
        split2(x0, h0, l0);
        split2(x1, h1, l1);
        uint32_t* o = wv2 + (size_t)e * LDKU + 3 * c;
        o[0] = h0 | (l0 << 16);
        o[1] = h0 | (h1 << 16);
        o[2] = l1 | (h1 << 16);
    }
}

// Assemble C = R1(upper,mirrored) + R2 + R2^T and pack as A-triplet rows.
__global__ void pack_ct(const float* __restrict__ R1, const float* __restrict__ R2,
                        uint32_t* __restrict__ out)
{
    int t = blockIdx.x * 256 + threadIdx.x;   // < 768*384
    const float* R1b = R1 + (size_t)blockIdx.y * Ev * Ev;
    const float* R2b = R2 + (size_t)blockIdx.y * Ev * Ev;
    uint32_t* ob = out + (size_t)blockIdx.y * Ev * LDKU;
    int e1 = t / 384, p = t % 384;
    int t1 = e1 >> 7;
    float v[2];
    #pragma unroll
    for (int q = 0; q < 2; q++) {
        int e2 = 2 * p + q;
        float r1 = (t1 <= (e2 >> 7)) ? R1b[(size_t)e1 * Ev + e2]
                                     : R1b[(size_t)e2 * Ev + e1];
        v[q] = r1 + R2b[(size_t)e1 * Ev + e2] + R2b[(size_t)e2 * Ev + e1];
    }
    uint32_t h0, l0, h1, l1;
    split2(v[0], h0, l0);
    split2(v[1], h1, l1);
    uint32_t* o = ob + (size_t)e1 * LDKU + 3 * p;
    o[0] = h0 | (h0 << 16);
    o[1] = l0 | (h1 << 16);
    o[2] = h1 | (l1 << 16);
}

// ---------------------------------------------------------------------------
// Fused G + norms + softmax + fold. One block per (b,h).
// Phase A: G_bh = Wq_h^T U, nq2/nk2 col-dots (from V2 = C @ [Wq|Wk]).
// Phase B: softmax in smem (attn stays resident).
// Phase C: P_b^T[n,(h,j)] = sum_i attn[i][j] * W_proj[(h,i), n], A-triplet out.
// ---------------------------------------------------------------------------
#define CH2 48
__global__ __launch_bounds__(256) void k_gsfold(
    const float* __restrict__ Wqkv, const float* __restrict__ V2,
    const float* __restrict__ temp, const float* __restrict__ Wp,
    uint32_t* __restrict__ Pt2)
{
    __shared__ float smA[4][Dv][CH2 + 1];   // phase A buffers; [0] becomes attn
    __shared__ float nr[96];
    float (*Wqs)[CH2 + 1] = smA[0];
    float (*Wks)[CH2 + 1] = smA[1];
    float (*Tqs)[CH2 + 1] = smA[2];
    float (*Us)[CH2 + 1]  = smA[3];
    float (*Gs)[CH2 + 1]  = smA[0];         // attn lives here after phase B
    float* Ws = &smA[1][0][0];              // phase C: 48x128 floats (6144 < 3*2352... fits in smA[1..3])

    const int bh = blockIdx.x;
    const int b = bh >> 4, h = bh & 15;
    const int tid = threadIdx.x;
    const int tx = tid & 15, ty = tid >> 4;

    float acc[3][3];
    #pragma unroll
    for (int r = 0; r < 3; r++)
        #pragma unroll
        for (int c = 0; c < 3; c++) acc[r][c] = 0.f;
    float na = 0.f;

    for (int e0 = 0; e0 < Ev; e0 += CH2) {
        for (int idx = tid; idx < Dv * CH2; idx += 256) {
            int i = idx % Dv, el = idx / Dv;
            int e = e0 + el;
            const float* wrow = Wqkv + (size_t)e * 2304 + h * Dv;
            const float* vrow = V2 + ((size_t)b * Ev + e) * 1536 + h * Dv;
            Wqs[i][el] = wrow[i];
            Wks[i][el] = wrow[768 + i];
            Tqs[i][el] = vrow[i];
            Us[i][el]  = vrow[768 + i];
        }
        __syncthreads();
        #pragma unroll 4
        for (int el = 0; el < CH2; el++) {
            float qv[3], uv[3];
            #pragma unroll
            for (int r = 0; r < 3; r++) qv[r] = Wqs[3 * ty + r][el];
            #pragma unroll
            for (int c = 0; c < 3; c++) uv[c] = Us[3 * tx + c][el];
            #pragma unroll
            for (int r = 0; r < 3; r++)
                #pragma unroll
                for (int c = 0; c < 3; c++)
                    acc[r][c] = fmaf(qv[r], uv[c], acc[r][c]);
        }
        if (tid < 2 * Dv) {
            float a = 0.f;
            if (tid < Dv) {
                #pragma unroll 8
                for (int el = 0; el < CH2; el++)
                    a = fmaf(Wqs[tid][el], Tqs[tid][el], a);
            } else {
                int j = tid - Dv;
                #pragma unroll 8
                for (int el = 0; el < CH2; el++)
                    a = fmaf(Wks[j][el], Us[j][el], a);
            }
            na += a;
        }
        __syncthreads();
    }
    #pragma unroll
    for (int r = 0; r < 3; r++)
        #pragma unroll
        for (int c = 0; c < 3; c++)
            Gs[3 * ty + r][3 * tx + c] = acc[r][c];
    if (tid < 96) nr[tid] = fmaxf(sqrtf(na), 1e-12f);
    __syncthreads();

    // softmax in-place in Gs
    const float T = temp[h];
    const int warp = tid >> 5, lane = tid & 31;
    for (int i = warp; i < Dv; i += 8) {
        float inq = T / nr[i];
        int j0 = lane, j1 = lane + 32;
        float v0 = Gs[i][j0] * inq / nr[Dv + j0];
        float v1 = (j1 < Dv) ? Gs[i][j1] * inq / nr[Dv + j1] : -INFINITY;
        float m = fmaxf(v0, v1);
        #pragma unroll
        for (int o = 16; o; o >>= 1) m = fmaxf(m, __shfl_xor_sync(~0u, m, o));
        float e0 = expf(v0 - m);
        float e1 = (j1 < Dv) ? expf(v1 - m) : 0.f;
        float ss = e0 + e1;
        #pragma unroll
        for (int o = 16; o; o >>= 1) ss += __shfl_xor_sync(~0u, ss, o);
        float inv = 1.f / ss;
        Gs[i][j0] = e0 * inv;
        if (j1 < Dv) Gs[i][j1] = e1 * inv;
    }
    __syncthreads();

    // fold: 6 n-blocks of 128 columns each
    const int ftx = tid & 127;      // n within block
    const int ftz = tid >> 7;       // j half (24 each)
    uint32_t* Pb = Pt2 + (size_t)b * Ev * LDKU;
    for (int nb = 0; nb < 6; nb++) {
        for (int idx = tid; idx < Dv * 128; idx += 256) {
            int i = idx >> 7, c = idx & 127;
            Ws[i * 128 + c] = Wp[(size_t)(h * Dv + i) * Ev + nb * 128 + c];
        }
        __syncthreads();
        float fa[24];
        #pragma unroll
        for (int j = 0; j < 24; j++) fa[j] = 0.f;
        #pragma unroll 4
        for (int i = 0; i < Dv; i++) {
            float a = Ws[i * 128 + ftx];
            #pragma unroll
            for (int j = 0; j < 24; j++)
                fa[j] = fmaf(Gs[i][ftz * 24 + j], a, fa[j]);
        }
        int n = nb * 128 + ftx;
        uint32_t* ob = Pb + (size_t)n * LDKU;
        #pragma unroll
        for (int t = 0; t < 12; t++) {
            uint32_t h0, l0, h1, l1;
            split2(fa[2 * t], h0, l0);
            split2(fa[2 * t + 1], h1, l1);
            uint32_t* o = ob + 3 * (h * 24 + ftz * 12 + t);
            o[0] = h0 | (h0 << 16);   // A layout
            o[1] = l0 | (h1 << 16);
            o[2] = h1 | (l1 << 16);
        }
        __syncthreads();
    }
}

// ---------------------------------------------------------------------------
// Launch
// ---------------------------------------------------------------------------
extern "C" void kernel_launch(void* const* d_in, const int* in_sizes, int n_in,
                              void* d_out, int out_size)
{
    const float* x      = (const float*)d_in[0];
    const float* W_qkv  = (const float*)d_in[1];
    const float* W_proj = (const float*)d_in[2];
    const float* b_proj = (const float*)d_in[3];
    const float* temp   = (const float*)d_in[4];
    float* outp = (float*)d_out;

    uint32_t *x2, *xtH, *xtL, *Cp, *wt1, *wv2, *Pt2, *wbT;
    float *R1, *R2, *V2;
    cudaGetSymbolAddress((void**)&x2, g_x2);
    cudaGetSymbolAddress((void**)&xtH, g_xtH);
    cudaGetSymbolAddress((void**)&xtL, g_xtL);
    cudaGetSymbolAddress((void**)&Cp, g_Cp);
    cudaGetSymbolAddress((void**)&wt1, g_wt1);
    cudaGetSymbolAddress((void**)&wv2, g_wv2);
    cudaGetSymbolAddress((void**)&Pt2, g_Pt2);
    cudaGetSymbolAddress((void**)&wbT, g_wbT);
    cudaGetSymbolAddress((void**)&R1, g_R1);
    cudaGetSymbolAddress((void**)&R2, g_R2);
    cudaGetSymbolAddress((void**)&V2, g_V2);

    cudaFuncSetAttribute(gemm_mma, cudaFuncAttributeMaxDynamicSharedMemorySize,
                         GEMM_SMEM);

    // packing
    {
        dim3 grid(12, 49, 16);
        pack_x<<<grid, 256>>>(x, x2, xtH, xtL);
    }
    pack_w<<<((1536 + 768) * 384) / 256, 256>>>(W_qkv, wt1, wv2);

    // merged: R1 = H^T H (triangular, 21 tiles) + R2 = H^T L (36 tiles)
    {
        dim3 grid(21 + 36, 16);
        gemm_mma<<<grid, 256, GEMM_SMEM>>>(
            (const char*)xtH, (const char*)xtH, R1, nullptr, Ev, 6,
            (size_t)Ev * LDH, (size_t)Ev * LDH, (size_t)Ev * Ev,
            1 << 30, LDH, 49, 21, (const char*)xtL, R2, 0);
    }
    // C = R1 + R2 + R2^T, packed A-triplet
    {
        dim3 grid(1152, 16);
        pack_ct<<<grid, 256>>>(R1, R2, Cp);
    }
    // V2 = C @ [Wq|Wk]
    {
        dim3 grid(6 * 12, 16);
        gemm_mma<<<grid, 256, GEMM_SMEM>>>(
            (const char*)Cp, (const char*)wt1, V2, nullptr, 1536, 12,
            (size_t)Ev * LDK, 0, (size_t)Ev * 1536, 1 << 30, LDK, 36, 0,
            nullptr, nullptr, 0);
    }
    // G + norms + softmax + fold (fused)
    k_gsfold<<<256, 256>>>(W_qkv, V2, temp, W_proj, Pt2);

    // WbT[n,e] = sum_m Pt[n,m] Wv[e,m] — packed triplet epilogue
    {
        dim3 grid(36, 16);
        gemm_mma<<<grid, 256, GEMM_SMEM>>>(
            (const char*)Pt2, (const char*)wv2, (float*)wbT, nullptr, Ev, 6,
            (size_t)Ev * LDKU * 4, 0, (size_t)Ev * LDKU, 1 << 30, LDK, 36, 0,
            nullptr, nullptr, 1);
    }
    // final: out_b = X_b @ W_b + b_proj
    {
        dim3 grid(25 * 6, 16);
        gemm_mma<<<grid, 256, GEMM_SMEM>>>(
            (const char*)x2, (const char*)wbT, outp, b_proj, Ev, 6,
            (size_t)Sv * LDK, (size_t)Ev * LDKU * 4, (size_t)Sv * Ev,
            Sv, LDK, 36, 0, nullptr, nullptr, 0);
    }
}

// round 14
// speedup vs baseline: 1.1132x; 1.1132x over previous
#include <cuda_runtime.h>
#include <cuda_bf16.h>
#include <math.h>
#include <stdint.h>

// ---------------- problem constants ----------------
#define Bv 16
#define Sv 3136
#define Ev 768
#define Hv 16
#define Dv 48
#define NTOK (Bv * Sv)      // 50176
#define LDP 3072            // bytes per packed row: [hi(768)|lo(768)] bf16
#define LDPU 768            // u32 per packed row
#define LDH 6272            // bytes per plain-bf16 row, K=3136
#define LDHU 1568           // u32 per plain row
#define NSTG 3
#define STG_BYTES 32768
#define GEMM_SMEM (NSTG * STG_BYTES)   // 98304

// ---------------- scratch (device globals) ----------------
__device__ uint32_t g_x2[(size_t)(NTOK + 128) * LDPU]; // packed x rows [hi|lo]
__device__ uint32_t g_xtH[(size_t)Bv * Ev * LDHU];     // X^T hi, plain bf16
__device__ uint32_t g_xtL[(size_t)Bv * Ev * LDHU];     // X^T lo, plain bf16
__device__ float    g_R1[(size_t)Bv * Ev * Ev];        // H^T H (upper tiles)
__device__ float    g_R2[(size_t)Bv * Ev * Ev];        // H^T L (full)
__device__ uint32_t g_Cp[(size_t)Bv * Ev * LDPU];      // C packed [hi|lo]
__device__ float    g_V2[(size_t)Bv * Ev * 1536];      // C @ [Wq|Wk]
__device__ uint32_t g_wt1[(size_t)1536 * LDPU];        // [Wq|Wk]^T packed
__device__ uint32_t g_wv2[(size_t)Ev * LDPU];          // Wv rows packed
__device__ uint32_t g_Pt2[(size_t)Bv * Ev * LDPU];     // P_b^T packed
__device__ uint32_t g_wbT[(size_t)Bv * Ev * LDPU];     // W_b^T packed

// ---------------- helpers ----------------
__device__ __forceinline__ uint32_t s2u(const void* p) {
    uint32_t a;
    asm("{ .reg .u64 t; cvta.to.shared.u64 t, %1; cvt.u32.u64 %0, t; }"
        : "=r"(a) : "l"(p));
    return a;
}
#define SWZ(o) ((o) ^ (((o) >> 3) & 0x70))

__device__ __forceinline__ void cpasync16(uint32_t s, const void* g) {
    asm volatile("cp.async.cg.shared.global [%0], [%1], 16;\n" :: "r"(s), "l"(g));
}
__device__ __forceinline__ void cp_commit() {
    asm volatile("cp.async.commit_group;\n");
}
template <int N> __device__ __forceinline__ void cp_wait() {
    asm volatile("cp.async.wait_group %0;\n" :: "n"(N));
}
__device__ __forceinline__ void ldm4(uint32_t& r0, uint32_t& r1, uint32_t& r2,
                                     uint32_t& r3, uint32_t a) {
    asm volatile("ldmatrix.sync.aligned.m8n8.x4.shared.b16 {%0,%1,%2,%3}, [%4];"
                 : "=r"(r0), "=r"(r1), "=r"(r2), "=r"(r3) : "r"(a));
}
__device__ __forceinline__ void mma16816(float* d, const uint32_t* a,
                                         const uint32_t* b) {
    asm volatile(
        "mma.sync.aligned.m16n8k16.row.col.f32.bf16.bf16.f32 "
        "{%0,%1,%2,%3}, {%4,%5,%6,%7}, {%8,%9}, {%0,%1,%2,%3};"
        : "+f"(d[0]), "+f"(d[1]), "+f"(d[2]), "+f"(d[3])
        : "r"(a[0]), "r"(a[1]), "r"(a[2]), "r"(a[3]), "r"(b[0]), "r"(b[1]));
}
__device__ __forceinline__ void split2(float x, uint32_t& h, uint32_t& l) {
    __nv_bfloat16 hb = __float2bfloat16(x);
    float rem = x - __bfloat162float(hb);
    __nv_bfloat16 lb = __float2bfloat16(rem);
    h = (uint32_t)__bfloat16_as_ushort(hb);
    l = (uint32_t)__bfloat16_as_ushort(lb);
}

// ---------------------------------------------------------------------------
// bf16 mma.sync GEMM (proven config). Extensions:
//  tri>0 : merged launch (triangular HtH tiles then rectangular HtL tiles).
//  tripK : 36 logical chunks over [hi|lo] storage; A map (c<12?c:c-12),
//          B map (c<24?c:c-24) -> products hi*hi, hi*lo, lo*hi.
//  packC : epilogue writes [hi|lo] bf16 rows into (uint32_t*)C.
// ---------------------------------------------------------------------------
__global__ __launch_bounds__(256, 2) void gemm_mma(
    const char* __restrict__ A, const char* __restrict__ B,
    float* __restrict__ C, const float* __restrict__ bias, int N, int NT,
    size_t aStride, size_t bStride, size_t cStride, int Mrows,
    int kRowBytes, int nkch, int tri, int tripK,
    const char* __restrict__ Balt, float* __restrict__ Calt, int packC)
{
    extern __shared__ char sm[];
    const int tid  = threadIdx.x;
    const int wid  = tid >> 5, lane = tid & 31;
    const int wm   = wid & 3;
    const int wn   = wid >> 2;
    const int bat  = blockIdx.y;
    int bm, bn;
    const char* Bsel = B;
    float* Csel = C;
    if (tri > 0) {
        if ((int)blockIdx.x < tri) {
            int t = blockIdx.x, r = 0, rl = 6;
            while (t >= rl) { t -= rl; rl--; r++; }
            bm = r; bn = r + t;
        } else {
            int t = blockIdx.x - tri;
            bm = t / 6; bn = t % 6;
            Bsel = Balt; Csel = Calt;
        }
    } else {
        bm = blockIdx.x / NT; bn = blockIdx.x % NT;
    }
    const uint32_t smb = s2u(sm);

    const char* Ab = A + (size_t)bat * aStride + (size_t)bm * 128 * kRowBytes;
    const char* Bb = Bsel + (size_t)bat * bStride + (size_t)bn * 128 * kRowBytes;

    const int ldr = tid >> 1;
    const int ldc = (tid & 1) * 64;

    auto loadch = [&](int sp, int ck) {
        uint32_t sa = smb + sp * STG_BYTES;
        uint32_t sb = sa + 16384;
        int ca = ck, cb = ck;
        if (tripK) {
            ca = (ck < 12) ? ck : ck - 12;
            cb = (ck < 24) ? ck : ck - 24;
        }
        const char* a0 = Ab + ca * 128;
        const char* b0 = Bb + cb * 128;
        #pragma unroll
        for (int i = 0; i < 4; i++) {
            int cbyte = ldc + i * 16;
            cpasync16(sa + SWZ(ldr * 128 + cbyte),
                      a0 + (size_t)ldr * kRowBytes + cbyte);
            cpasync16(sb + SWZ(ldr * 128 + cbyte),
                      b0 + (size_t)ldr * kRowBytes + cbyte);
        }
        cp_commit();
    };

    float acc[2][8][4];
    #pragma unroll
    for (int m = 0; m < 2; m++)
        #pragma unroll
        for (int n = 0; n < 8; n++)
            #pragma unroll
            for (int p = 0; p < 4; p++) acc[m][n][p] = 0.f;

    loadch(0, 0);
    loadch(1, 1);

    const int a_row = (lane & 7) + ((lane >> 3) & 1) * 8;
    const int a_cb  = (lane >> 4) * 16;
    const int b_row = (lane & 7) + (lane >> 4) * 8;
    const int b_cb  = ((lane >> 3) & 1) * 16;

    uint32_t af[2][2][4], bf[2][8][2];

    auto ldfrag = [&](uint32_t sa, uint32_t sb, int ks, int buf) {
        #pragma unroll
        for (int mb = 0; mb < 2; mb++) {
            int r = wm * 32 + mb * 16 + a_row;
            ldm4(af[buf][mb][0], af[buf][mb][1], af[buf][mb][2], af[buf][mb][3],
                 sa + SWZ(r * 128 + ks * 32 + a_cb));
        }
        #pragma unroll
        for (int nb2 = 0; nb2 < 4; nb2++) {
            int r = wn * 64 + nb2 * 16 + b_row;
            ldm4(bf[buf][2 * nb2][0], bf[buf][2 * nb2][1],
                 bf[buf][2 * nb2 + 1][0], bf[buf][2 * nb2 + 1][1],
                 sb + SWZ(r * 128 + ks * 32 + b_cb));
        }
    };

    for (int k = 0; k < nkch; k++) {
        cp_wait<1>();
        __syncthreads();

        int kp = k + 2;
        if (kp < nkch) loadch(kp % NSTG, kp);
        else cp_commit();

        uint32_t sa = smb + (k % NSTG) * STG_BYTES;
        uint32_t sb = sa + 16384;

        ldfrag(sa, sb, 0, 0);
        #pragma unroll
        for (int ks = 0; ks < 4; ks++) {
            int c = ks & 1;
            if (ks < 3) ldfrag(sa, sb, ks + 1, c ^ 1);
            #pragma unroll
            for (int mb = 0; mb < 2; mb++)
                #pragma unroll
                for (int nb = 0; nb < 8; nb++)
                    mma16816(acc[mb][nb], af[c][mb], bf[c][nb]);
        }
    }

    const int er = lane >> 2;
    const int ec = (lane & 3) * 2;
    const int rbase = bm * 128 + wm * 32;

    if (packC) {
        // write [hi|lo] rows: hi pair at (col>>1), lo pair at 384+(col>>1)
        uint32_t* Cpk = (uint32_t*)Csel + (size_t)bat * cStride;
        #pragma unroll
        for (int mb = 0; mb < 2; mb++) {
            int r0 = rbase + mb * 16 + er;
            #pragma unroll
            for (int nb = 0; nb < 8; nb++) {
                int col = bn * 128 + wn * 64 + nb * 8 + ec;   // even
                uint32_t h0, l0, h1, l1;
                split2(acc[mb][nb][0], h0, l0);
                split2(acc[mb][nb][1], h1, l1);
                uint32_t* o = Cpk + (size_t)r0 * LDPU + (col >> 1);
                o[0]   = h0 | (h1 << 16);
                o[384] = l0 | (l1 << 16);
                split2(acc[mb][nb][2], h0, l0);
                split2(acc[mb][nb][3], h1, l1);
                uint32_t* o2 = Cpk + (size_t)(r0 + 8) * LDPU + (col >> 1);
                o2[0]   = h0 | (h1 << 16);
                o2[384] = l0 | (l1 << 16);
            }
        }
        return;
    }

    float* Cb = Csel + (size_t)bat * cStride
                + (size_t)rbase * N + (size_t)bn * 128 + wn * 64;
    float bvs[8][2];
    #pragma unroll
    for (int nb = 0; nb < 8; nb++) {
        if (bias) {
            const float* bp = bias + (size_t)bn * 128 + wn * 64 + nb * 8 + ec;
            bvs[nb][0] = bp[0]; bvs[nb][1] = bp[1];
        } else { bvs[nb][0] = 0.f; bvs[nb][1] = 0.f; }
    }
    #pragma unroll
    for (int mb = 0; mb < 2; mb++) {
        int r0 = rbase + mb * 16 + er;
        bool w0 = r0 < Mrows, w1 = (r0 + 8) < Mrows;
        #pragma unroll
        for (int nb = 0; nb < 8; nb++) {
            int col = nb * 8 + ec;
            float2 v0 = {acc[mb][nb][0] + bvs[nb][0], acc[mb][nb][1] + bvs[nb][1]};
            float2 v1 = {acc[mb][nb][2] + bvs[nb][0], acc[mb][nb][3] + bvs[nb][1]};
            if (w0) *(float2*)(Cb + (size_t)(mb * 16 + er) * N + col) = v0;
            if (w1) *(float2*)(Cb + (size_t)(mb * 16 + er + 8) * N + col) = v1;
        }
    }
}

// ---------------------------------------------------------------------------
// Fused X packing: x2 ([hi|lo] rows), xtH, xtL (transposed plain hi/lo).
// grid = (12 e-tiles, 49 s-tiles, 16 b).
// ---------------------------------------------------------------------------
__global__ __launch_bounds__(256) void pack_x(
    const float* __restrict__ x, uint32_t* __restrict__ x2,
    uint32_t* __restrict__ xtH, uint32_t* __restrict__ xtL)
{
    __shared__ float ts[64][65];
    const int e0 = blockIdx.x * 64, s0 = blockIdx.y * 64, b = blockIdx.z;
    const int tid = threadIdx.x;
    #pragma unroll
    for (int i = 0; i < 16; i++) {
        int idx = tid + i * 256;
        int sl = idx >> 6, el = idx & 63;
        ts[sl][el] = x[((size_t)b * Sv + s0 + sl) * Ev + e0 + el];
    }
    __syncthreads();
    #pragma unroll
    for (int i = 0; i < 8; i++) {
        int item = tid + i * 256;
        int el = item >> 5, sp = item & 31;
        float v0 = ts[2 * sp][el], v1 = ts[2 * sp + 1][el];
        uint32_t h0, l0, h1, l1;
        split2(v0, h0, l0);
        split2(v1, h1, l1);
        size_t r = ((size_t)b * Ev + e0 + el) * LDHU + (s0 >> 1) + sp;
        xtH[r] = h0 | (h1 << 16);
        xtL[r] = l0 | (l1 << 16);
    }
    #pragma unroll
    for (int i = 0; i < 8; i++) {
        int item = tid + i * 256;
        int sl = item >> 5, pe = item & 31;
        float v0 = ts[sl][2 * pe], v1 = ts[sl][2 * pe + 1];
        uint32_t h0, l0, h1, l1;
        split2(v0, h0, l0);
        split2(v1, h1, l1);
        uint32_t* row = x2 + ((size_t)b * Sv + s0 + sl) * LDPU;
        int p = (e0 >> 1) + pe;
        row[p]       = h0 | (h1 << 16);
        row[384 + p] = l0 | (l1 << 16);
    }
}

// ---------------------------------------------------------------------------
// Merged weight packing: [Wq|Wk]^T (1536 rows) and Wv rows (768 rows),
// both in [hi|lo] storage.
// ---------------------------------------------------------------------------
__global__ void pack_w(const float* __restrict__ Wqkv,
                       uint32_t* __restrict__ wt1, uint32_t* __restrict__ wv2)
{
    int t = blockIdx.x * 256 + threadIdx.x;
    const int NW = 1536 * 384;
    if (t < NW) {
        int n = t / 384, kp = t % 384;
        float x0 = Wqkv[(size_t)(2 * kp) * 2304 + n];
        float x1 = Wqkv[(size_t)(2 * kp + 1) * 2304 + n];
        uint32_t h0, l0, h1, l1;
        split2(x0, h0, l0);
        split2(x1, h1, l1);
        uint32_t* o = wt1 + (size_t)n * LDPU + kp;
        o[0]   = h0 | (h1 << 16);
        o[384] = l0 | (l1 << 16);
    } else {
        int t2 = t - NW;
        if (t2 >= Ev * 384) return;
        int e = t2 / 384, c = t2 % 384;
        float x0 = Wqkv[(size_t)e * 2304 + 1536 + 2 * c];
        float x1 = Wqkv[(size_t)e * 2304 + 1536 + 2 * c + 1];
        uint32_t h0, l0, h1, l1;
        split2(x0, h0, l0);
        split2(x1, h1, l1);
        uint32_t* o = wv2 + (size_t)e * LDPU + c;
        o[0]   = h0 | (h1 << 16);
        o[384] = l0 | (l1 << 16);
    }
}

// ---------------------------------------------------------------------------
// Assemble C = R1(mirrored upper) + R2 + R2^T, pack [hi|lo] rows.
// Coalesced: transposed operands staged through 64x64 smem tiles.
// grid = (144 64x64-tiles, 16 batches); tile (tm, tn) of 12x12.
// ---------------------------------------------------------------------------
__global__ __launch_bounds__(256) void pack_ct(
    const float* __restrict__ R1, const float* __restrict__ R2,
    uint32_t* __restrict__ out)
{
    __shared__ float T2s[64][65];
    __shared__ float T1s[64][65];
    const int tm = blockIdx.x / 12, tn = blockIdx.x % 12;
    const int b = blockIdx.y;
    const int tid = threadIdx.x;
    const float* R1b = R1 + (size_t)b * Ev * Ev;
    const float* R2b = R2 + (size_t)b * Ev * Ev;
    uint32_t* ob = out + (size_t)b * Ev * LDPU;
    const bool r1dir = (tm >> 1) <= (tn >> 1);

    for (int idx = tid; idx < 64 * 64; idx += 256) {
        int r = idx >> 6, c = idx & 63;
        T2s[r][c] = R2b[(size_t)(tn * 64 + r) * Ev + tm * 64 + c];
    }
    if (!r1dir) {
        for (int idx = tid; idx < 64 * 64; idx += 256) {
            int r = idx >> 6, c = idx & 63;
            T1s[r][c] = R1b[(size_t)(tn * 64 + r) * Ev + tm * 64 + c];
        }
    }
    __syncthreads();

    for (int idx = tid; idx < 64 * 32; idx += 256) {
        int r = idx >> 5, p = idx & 31;
        int e1 = tm * 64 + r;
        int e2 = tn * 64 + 2 * p;
        float d0 = R2b[(size_t)e1 * Ev + e2];
        float d1 = R2b[(size_t)e1 * Ev + e2 + 1];
        float r10 = r1dir ? R1b[(size_t)e1 * Ev + e2]     : T1s[2 * p][r];
        float r11 = r1dir ? R1b[(size_t)e1 * Ev + e2 + 1] : T1s[2 * p + 1][r];
        float v0 = r10 + d0 + T2s[2 * p][r];
        float v1 = r11 + d1 + T2s[2 * p + 1][r];
        uint32_t h0, l0, h1, l1;
        split2(v0, h0, l0);
        split2(v1, h1, l1);
        uint32_t* o = ob + (size_t)e1 * LDPU + tn * 32 + p;
        o[0]   = h0 | (h1 << 16);
        o[384] = l0 | (l1 << 16);
    }
}

// ---------------------------------------------------------------------------
// Fused G + norms + softmax + fold. One block per (b,h).
// ---------------------------------------------------------------------------
#define CH2 48
__global__ __launch_bounds__(256) void k_gsfold(
    const float* __restrict__ Wqkv, const float* __restrict__ V2,
    const float* __restrict__ temp, const float* __restrict__ Wp,
    uint32_t* __restrict__ Pt2)
{
    __shared__ float smA[4][Dv][CH2 + 1];
    __shared__ float nr[96];
    float (*Wqs)[CH2 + 1] = smA[0];
    float (*Wks)[CH2 + 1] = smA[1];
    float (*Tqs)[CH2 + 1] = smA[2];
    float (*Us)[CH2 + 1]  = smA[3];
    float (*Gs)[CH2 + 1]  = smA[0];
    float* Ws = &smA[1][0][0];

    const int bh = blockIdx.x;
    const int b = bh >> 4, h = bh & 15;
    const int tid = threadIdx.x;
    const int tx = tid & 15, ty = tid >> 4;

    float acc[3][3];
    #pragma unroll
    for (int r = 0; r < 3; r++)
        #pragma unroll
        for (int c = 0; c < 3; c++) acc[r][c] = 0.f;
    float na = 0.f;

    for (int e0 = 0; e0 < Ev; e0 += CH2) {
        for (int idx = tid; idx < Dv * CH2; idx += 256) {
            int i = idx % Dv, el = idx / Dv;
            int e = e0 + el;
            const float* wrow = Wqkv + (size_t)e * 2304 + h * Dv;
            const float* vrow = V2 + ((size_t)b * Ev + e) * 1536 + h * Dv;
            Wqs[i][el] = wrow[i];
            Wks[i][el] = wrow[768 + i];
            Tqs[i][el] = vrow[i];
            Us[i][el]  = vrow[768 + i];
        }
        __syncthreads();
        #pragma unroll 4
        for (int el = 0; el < CH2; el++) {
            float qv[3], uv[3];
            #pragma unroll
            for (int r = 0; r < 3; r++) qv[r] = Wqs[3 * ty + r][el];
            #pragma unroll
            for (int c = 0; c < 3; c++) uv[c] = Us[3 * tx + c][el];
            #pragma unroll
            for (int r = 0; r < 3; r++)
                #pragma unroll
                for (int c = 0; c < 3; c++)
                    acc[r][c] = fmaf(qv[r], uv[c], acc[r][c]);
        }
        if (tid < 2 * Dv) {
            float a = 0.f;
            if (tid < Dv) {
                #pragma unroll 8
                for (int el = 0; el < CH2; el++)
                    a = fmaf(Wqs[tid][el], Tqs[tid][el], a);
            } else {
                int j = tid - Dv;
                #pragma unroll 8
                for (int el = 0; el < CH2; el++)
                    a = fmaf(Wks[j][el], Us[j][el], a);
            }
            na += a;
        }
        __syncthreads();
    }
    #pragma unroll
    for (int r = 0; r < 3; r++)
        #pragma unroll
        for (int c = 0; c < 3; c++)
            Gs[3 * ty + r][3 * tx + c] = acc[r][c];
    if (tid < 96) nr[tid] = fmaxf(sqrtf(na), 1e-12f);
    __syncthreads();

    const float T = temp[h];
    const int warp = tid >> 5, lane = tid & 31;
    for (int i = warp; i < Dv; i += 8) {
        float inq = T / nr[i];
        int j0 = lane, j1 = lane + 32;
        float v0 = Gs[i][j0] * inq / nr[Dv + j0];
        float v1 = (j1 < Dv) ? Gs[i][j1] * inq / nr[Dv + j1] : -INFINITY;
        float m = fmaxf(v0, v1);
        #pragma unroll
        for (int o = 16; o; o >>= 1) m = fmaxf(m, __shfl_xor_sync(~0u, m, o));
        float e0 = expf(v0 - m);
        float e1 = (j1 < Dv) ? expf(v1 - m) : 0.f;
        float ss = e0 + e1;
        #pragma unroll
        for (int o = 16; o; o >>= 1) ss += __shfl_xor_sync(~0u, ss, o);
        float inv = 1.f / ss;
        Gs[i][j0] = e0 * inv;
        if (j1 < Dv) Gs[i][j1] = e1 * inv;
    }
    __syncthreads();

    // fold: P_b^T[n,(h,j)] = sum_i attn[i][j] * Wp[(h,i), n], [hi|lo] out
    const int ftx = tid & 127;
    const int ftz = tid >> 7;
    uint32_t* Pb = Pt2 + (size_t)b * Ev * LDPU;
    for (int nb = 0; nb < 6; nb++) {
        for (int idx = tid; idx < Dv * 128; idx += 256) {
            int i = idx >> 7, c = idx & 127;
            Ws[i * 128 + c] = Wp[(size_t)(h * Dv + i) * Ev + nb * 128 + c];
        }
        __syncthreads();
        float fa[24];
        #pragma unroll
        for (int j = 0; j < 24; j++) fa[j] = 0.f;
        #pragma unroll 4
        for (int i = 0; i < Dv; i++) {
            float a = Ws[i * 128 + ftx];
            #pragma unroll
            for (int j = 0; j < 24; j++)
                fa[j] = fmaf(Gs[i][ftz * 24 + j], a, fa[j]);
        }
        int n = nb * 128 + ftx;
        uint32_t* ob = Pb + (size_t)n * LDPU;
        #pragma unroll
        for (int t = 0; t < 12; t++) {
            uint32_t h0, l0, h1, l1;
            split2(fa[2 * t], h0, l0);
            split2(fa[2 * t + 1], h1, l1);
            int p = h * 24 + ftz * 12 + t;
            ob[p]       = h0 | (h1 << 16);
            ob[384 + p] = l0 | (l1 << 16);
        }
        __syncthreads();
    }
}

// ---------------------------------------------------------------------------
// Launch
// ---------------------------------------------------------------------------
extern "C" void kernel_launch(void* const* d_in, const int* in_sizes, int n_in,
                              void* d_out, int out_size)
{
    const float* x      = (const float*)d_in[0];
    const float* W_qkv  = (const float*)d_in[1];
    const float* W_proj = (const float*)d_in[2];
    const float* b_proj = (const float*)d_in[3];
    const float* temp   = (const float*)d_in[4];
    float* outp = (float*)d_out;

    uint32_t *x2, *xtH, *xtL, *Cp, *wt1, *wv2, *Pt2, *wbT;
    float *R1, *R2, *V2;
    cudaGetSymbolAddress((void**)&x2, g_x2);
    cudaGetSymbolAddress((void**)&xtH, g_xtH);
    cudaGetSymbolAddress((void**)&xtL, g_xtL);
    cudaGetSymbolAddress((void**)&Cp, g_Cp);
    cudaGetSymbolAddress((void**)&wt1, g_wt1);
    cudaGetSymbolAddress((void**)&wv2, g_wv2);
    cudaGetSymbolAddress((void**)&Pt2, g_Pt2);
    cudaGetSymbolAddress((void**)&wbT, g_wbT);
    cudaGetSymbolAddress((void**)&R1, g_R1);
    cudaGetSymbolAddress((void**)&R2, g_R2);
    cudaGetSymbolAddress((void**)&V2, g_V2);

    cudaFuncSetAttribute(gemm_mma, cudaFuncAttributeMaxDynamicSharedMemorySize,
                         GEMM_SMEM);

    // packing
    {
        dim3 grid(12, 49, 16);
        pack_x<<<grid, 256>>>(x, x2, xtH, xtL);
    }
    pack_w<<<((1536 + 768) * 384) / 256, 256>>>(W_qkv, wt1, wv2);

    // merged: R1 = H^T H (triangular, 21 tiles) + R2 = H^T L (36 tiles)
    {
        dim3 grid(21 + 36, 16);
        gemm_mma<<<grid, 256, GEMM_SMEM>>>(
            (const char*)xtH, (const char*)xtH, R1, nullptr, Ev, 6,
            (size_t)Ev * LDH, (size_t)Ev * LDH, (size_t)Ev * Ev,
            1 << 30, LDH, 49, 21, 0, (const char*)xtL, R2, 0);
    }
    // C = R1 + R2 + R2^T, packed [hi|lo] (coalesced via smem tiles)
    {
        dim3 grid(144, 16);
        pack_ct<<<grid, 256>>>(R1, R2, Cp);
    }
    // V2 = C @ [Wq|Wk]
    {
        dim3 grid(6 * 12, 16);
        gemm_mma<<<grid, 256, GEMM_SMEM>>>(
            (const char*)Cp, (const char*)wt1, V2, nullptr, 1536, 12,
            (size_t)Ev * LDP, 0, (size_t)Ev * 1536, 1 << 30, LDP, 36, 0, 1,
            nullptr, nullptr, 0);
    }
    // G + norms + softmax + fold (fused)
    k_gsfold<<<256, 256>>>(W_qkv, V2, temp, W_proj, Pt2);

    // WbT[n,e] = sum_m Pt[n,m] Wv[e,m] — packed [hi|lo] epilogue
    {
        dim3 grid(36, 16);
        gemm_mma<<<grid, 256, GEMM_SMEM>>>(
            (const char*)Pt2, (const char*)wv2, (float*)wbT, nullptr, Ev, 6,
            (size_t)Ev * LDP, 0, (size_t)Ev * LDPU, 1 << 30, LDP, 36, 0, 1,
            nullptr, nullptr, 1);
    }
    // final: out_b = X_b @ W_b + b_proj
    {
        dim3 grid(25 * 6, 16);
        gemm_mma<<<grid, 256, GEMM_SMEM>>>(
            (const char*)x2, (const char*)wbT, outp, b_proj, Ev, 6,
            (size_t)Sv * LDP, (size_t)Ev * LDP, (size_t)Sv * Ev,
            Sv, LDP, 36, 0, 1, nullptr, nullptr, 0);
    }
}

// round 15
// speedup vs baseline: 1.2630x; 1.1346x over previous
#include <cuda_runtime.h>
#include <cuda_bf16.h>
#include <cuda_fp16.h>
#include <math.h>
#include <stdint.h>

// ---------------- problem constants ----------------
#define Bv 16
#define Sv 3136
#define Ev 768
#define Hv 16
#define Dv 48
#define NTOK (Bv * Sv)      // 50176
#define LDP 3072            // bytes per packed row: [hi(768)|lo(768)]
#define LDPU 768            // u32 per packed row
#define LDH 6272            // bytes per plain-bf16 row, K=3136
#define LDHU 1568           // u32 per plain row
#define NSTG 3
#define STG_BYTES 32768
#define GEMM_SMEM (NSTG * STG_BYTES)   // 98304

// ---------------- scratch (device globals) ----------------
__device__ uint32_t g_x2[(size_t)(NTOK + 128) * LDPU]; // packed x rows (fp16 hi|lo)
__device__ uint32_t g_xtH[(size_t)Bv * Ev * LDHU];     // X^T hi, plain bf16
__device__ uint32_t g_xtL[(size_t)Bv * Ev * LDHU];     // X^T lo, plain bf16
__device__ float    g_R1[(size_t)Bv * Ev * Ev];        // H^T H (upper tiles)
__device__ float    g_R2[(size_t)Bv * Ev * Ev];        // H^T L (full)
__device__ uint32_t g_Cp[(size_t)Bv * Ev * LDPU];      // C packed bf16 [hi|lo]
__device__ float    g_V2[(size_t)Bv * Ev * 1536];      // C @ [Wq|Wk]
__device__ uint32_t g_wt1[(size_t)1536 * LDPU];        // [Wq|Wk]^T packed bf16
__device__ uint32_t g_wv2[(size_t)Ev * LDPU];          // Wv rows packed bf16
__device__ uint32_t g_Pt2[(size_t)Bv * Ev * LDPU];     // P_b^T packed bf16
__device__ uint32_t g_wbT[(size_t)Bv * Ev * LDPU];     // W_b^T packed fp16 hi|lo

// ---------------- helpers ----------------
__device__ __forceinline__ uint32_t s2u(const void* p) {
    uint32_t a;
    asm("{ .reg .u64 t; cvta.to.shared.u64 t, %1; cvt.u32.u64 %0, t; }"
        : "=r"(a) : "l"(p));
    return a;
}
#define SWZ(o) ((o) ^ (((o) >> 3) & 0x70))

__device__ __forceinline__ void cpasync16(uint32_t s, const void* g) {
    asm volatile("cp.async.cg.shared.global [%0], [%1], 16;\n" :: "r"(s), "l"(g));
}
__device__ __forceinline__ void cp_commit() {
    asm volatile("cp.async.commit_group;\n");
}
template <int N> __device__ __forceinline__ void cp_wait() {
    asm volatile("cp.async.wait_group %0;\n" :: "n"(N));
}
__device__ __forceinline__ void ldm4(uint32_t& r0, uint32_t& r1, uint32_t& r2,
                                     uint32_t& r3, uint32_t a) {
    asm volatile("ldmatrix.sync.aligned.m8n8.x4.shared.b16 {%0,%1,%2,%3}, [%4];"
                 : "=r"(r0), "=r"(r1), "=r"(r2), "=r"(r3) : "r"(a));
}
template <bool F16>
__device__ __forceinline__ void mma16816(float* d, const uint32_t* a,
                                         const uint32_t* b) {
    if constexpr (F16) {
        asm volatile(
            "mma.sync.aligned.m16n8k16.row.col.f32.f16.f16.f32 "
            "{%0,%1,%2,%3}, {%4,%5,%6,%7}, {%8,%9}, {%0,%1,%2,%3};"
            : "+f"(d[0]), "+f"(d[1]), "+f"(d[2]), "+f"(d[3])
            : "r"(a[0]), "r"(a[1]), "r"(a[2]), "r"(a[3]), "r"(b[0]), "r"(b[1]));
    } else {
        asm volatile(
            "mma.sync.aligned.m16n8k16.row.col.f32.bf16.bf16.f32 "
            "{%0,%1,%2,%3}, {%4,%5,%6,%7}, {%8,%9}, {%0,%1,%2,%3};"
            : "+f"(d[0]), "+f"(d[1]), "+f"(d[2]), "+f"(d[3])
            : "r"(a[0]), "r"(a[1]), "r"(a[2]), "r"(a[3]), "r"(b[0]), "r"(b[1]));
    }
}
__device__ __forceinline__ void split2(float x, uint32_t& h, uint32_t& l) {
    __nv_bfloat16 hb = __float2bfloat16(x);
    float rem = x - __bfloat162float(hb);
    __nv_bfloat16 lb = __float2bfloat16(rem);
    h = (uint32_t)__bfloat16_as_ushort(hb);
    l = (uint32_t)__bfloat16_as_ushort(lb);
}
__device__ __forceinline__ void split2h(float x, uint32_t& h, uint32_t& l) {
    __half hb = __float2half(x);
    float rem = x - __half2float(hb);
    __half lb = __float2half(rem);
    h = (uint32_t)__half_as_ushort(hb);
    l = (uint32_t)__half_as_ushort(lb);
}

// ---------------------------------------------------------------------------
// mma.sync GEMM (proven config), templated on element type (bf16/fp16).
//  tri>0  : merged launch (triangular HtH tiles then rectangular HtL tiles).
//  tripK=1: 36 chunks over [hi|lo]: A (c<12?c:c-12), B (c<24?c:c-24)
//           -> hi*hi, hi*lo, lo*hi (bf16 3-term).
//  tripK=2: 24 chunks: A (c<12?c:c-12), B (c) -> hi*hi, hi*lo (fp16 2-term).
//  packC=1: epilogue writes bf16 [hi|lo] rows; packC=2: fp16 [hi|lo] rows.
// ---------------------------------------------------------------------------
template <bool F16>
__global__ __launch_bounds__(256, 2) void gemm_mma(
    const char* __restrict__ A, const char* __restrict__ B,
    float* __restrict__ C, const float* __restrict__ bias, int N, int NT,
    size_t aStride, size_t bStride, size_t cStride, int Mrows,
    int kRowBytes, int nkch, int tri, int tripK,
    const char* __restrict__ Balt, float* __restrict__ Calt, int packC)
{
    extern __shared__ char sm[];
    const int tid  = threadIdx.x;
    const int wid  = tid >> 5, lane = tid & 31;
    const int wm   = wid & 3;
    const int wn   = wid >> 2;
    const int bat  = blockIdx.y;
    int bm, bn;
    const char* Bsel = B;
    float* Csel = C;
    if (tri > 0) {
        if ((int)blockIdx.x < tri) {
            int t = blockIdx.x, r = 0, rl = 6;
            while (t >= rl) { t -= rl; rl--; r++; }
            bm = r; bn = r + t;
        } else {
            int t = blockIdx.x - tri;
            bm = t / 6; bn = t % 6;
            Bsel = Balt; Csel = Calt;
        }
    } else {
        bm = blockIdx.x / NT; bn = blockIdx.x % NT;
    }
    const uint32_t smb = s2u(sm);

    const char* Ab = A + (size_t)bat * aStride + (size_t)bm * 128 * kRowBytes;
    const char* Bb = Bsel + (size_t)bat * bStride + (size_t)bn * 128 * kRowBytes;

    const int ldr = tid >> 1;
    const int ldc = (tid & 1) * 64;

    auto loadch = [&](int sp, int ck) {
        uint32_t sa = smb + sp * STG_BYTES;
        uint32_t sb = sa + 16384;
        int ca = ck, cb = ck;
        if (tripK == 1) {
            ca = (ck < 12) ? ck : ck - 12;
            cb = (ck < 24) ? ck : ck - 24;
        } else if (tripK == 2) {
            ca = (ck < 12) ? ck : ck - 12;
            cb = ck;
        }
        const char* a0 = Ab + ca * 128;
        const char* b0 = Bb + cb * 128;
        #pragma unroll
        for (int i = 0; i < 4; i++) {
            int cbyte = ldc + i * 16;
            cpasync16(sa + SWZ(ldr * 128 + cbyte),
                      a0 + (size_t)ldr * kRowBytes + cbyte);
            cpasync16(sb + SWZ(ldr * 128 + cbyte),
                      b0 + (size_t)ldr * kRowBytes + cbyte);
        }
        cp_commit();
    };

    float acc[2][8][4];
    #pragma unroll
    for (int m = 0; m < 2; m++)
        #pragma unroll
        for (int n = 0; n < 8; n++)
            #pragma unroll
            for (int p = 0; p < 4; p++) acc[m][n][p] = 0.f;

    loadch(0, 0);
    loadch(1, 1);

    const int a_row = (lane & 7) + ((lane >> 3) & 1) * 8;
    const int a_cb  = (lane >> 4) * 16;
    const int b_row = (lane & 7) + (lane >> 4) * 8;
    const int b_cb  = ((lane >> 3) & 1) * 16;

    uint32_t af[2][2][4], bf[2][8][2];

    auto ldfrag = [&](uint32_t sa, uint32_t sb, int ks, int buf) {
        #pragma unroll
        for (int mb = 0; mb < 2; mb++) {
            int r = wm * 32 + mb * 16 + a_row;
            ldm4(af[buf][mb][0], af[buf][mb][1], af[buf][mb][2], af[buf][mb][3],
                 sa + SWZ(r * 128 + ks * 32 + a_cb));
        }
        #pragma unroll
        for (int nb2 = 0; nb2 < 4; nb2++) {
            int r = wn * 64 + nb2 * 16 + b_row;
            ldm4(bf[buf][2 * nb2][0], bf[buf][2 * nb2][1],
                 bf[buf][2 * nb2 + 1][0], bf[buf][2 * nb2 + 1][1],
                 sb + SWZ(r * 128 + ks * 32 + b_cb));
        }
    };

    for (int k = 0; k < nkch; k++) {
        cp_wait<1>();
        __syncthreads();

        int kp = k + 2;
        if (kp < nkch) loadch(kp % NSTG, kp);
        else cp_commit();

        uint32_t sa = smb + (k % NSTG) * STG_BYTES;
        uint32_t sb = sa + 16384;

        ldfrag(sa, sb, 0, 0);
        #pragma unroll
        for (int ks = 0; ks < 4; ks++) {
            int c = ks & 1;
            if (ks < 3) ldfrag(sa, sb, ks + 1, c ^ 1);
            #pragma unroll
            for (int mb = 0; mb < 2; mb++)
                #pragma unroll
                for (int nb = 0; nb < 8; nb++)
                    mma16816<F16>(acc[mb][nb], af[c][mb], bf[c][nb]);
        }
    }

    const int er = lane >> 2;
    const int ec = (lane & 3) * 2;
    const int rbase = bm * 128 + wm * 32;

    if (packC) {
        uint32_t* Cpk = (uint32_t*)Csel + (size_t)bat * cStride;
        #pragma unroll
        for (int mb = 0; mb < 2; mb++) {
            int r0 = rbase + mb * 16 + er;
            #pragma unroll
            for (int nb = 0; nb < 8; nb++) {
                int col = bn * 128 + wn * 64 + nb * 8 + ec;   // even
                uint32_t h0, l0, h1, l1;
                if (packC == 2) { split2h(acc[mb][nb][0], h0, l0);
                                  split2h(acc[mb][nb][1], h1, l1); }
                else            { split2(acc[mb][nb][0], h0, l0);
                                  split2(acc[mb][nb][1], h1, l1); }
                uint32_t* o = Cpk + (size_t)r0 * LDPU + (col >> 1);
                o[0]   = h0 | (h1 << 16);
                o[384] = l0 | (l1 << 16);
                if (packC == 2) { split2h(acc[mb][nb][2], h0, l0);
                                  split2h(acc[mb][nb][3], h1, l1); }
                else            { split2(acc[mb][nb][2], h0, l0);
                                  split2(acc[mb][nb][3], h1, l1); }
                uint32_t* o2 = Cpk + (size_t)(r0 + 8) * LDPU + (col >> 1);
                o2[0]   = h0 | (h1 << 16);
                o2[384] = l0 | (l1 << 16);
            }
        }
        return;
    }

    float* Cb = Csel + (size_t)bat * cStride
                + (size_t)rbase * N + (size_t)bn * 128 + wn * 64;
    float bvs[8][2];
    #pragma unroll
    for (int nb = 0; nb < 8; nb++) {
        if (bias) {
            const float* bp = bias + (size_t)bn * 128 + wn * 64 + nb * 8 + ec;
            bvs[nb][0] = bp[0]; bvs[nb][1] = bp[1];
        } else { bvs[nb][0] = 0.f; bvs[nb][1] = 0.f; }
    }
    #pragma unroll
    for (int mb = 0; mb < 2; mb++) {
        int r0 = rbase + mb * 16 + er;
        bool w0 = r0 < Mrows, w1 = (r0 + 8) < Mrows;
        #pragma unroll
        for (int nb = 0; nb < 8; nb++) {
            int col = nb * 8 + ec;
            float2 v0 = {acc[mb][nb][0] + bvs[nb][0], acc[mb][nb][1] + bvs[nb][1]};
            float2 v1 = {acc[mb][nb][2] + bvs[nb][0], acc[mb][nb][3] + bvs[nb][1]};
            if (w0) *(float2*)(Cb + (size_t)(mb * 16 + er) * N + col) = v0;
            if (w1) *(float2*)(Cb + (size_t)(mb * 16 + er + 8) * N + col) = v1;
        }
    }
}

// ---------------------------------------------------------------------------
// Fused X packing: x2 = fp16 [hi|lo] rows; xtH/xtL = transposed plain bf16.
// grid = (12 e-tiles, 49 s-tiles, 16 b).
// ---------------------------------------------------------------------------
__global__ __launch_bounds__(256) void pack_x(
    const float* __restrict__ x, uint32_t* __restrict__ x2,
    uint32_t* __restrict__ xtH, uint32_t* __restrict__ xtL)
{
    __shared__ float ts[64][65];
    const int e0 = blockIdx.x * 64, s0 = blockIdx.y * 64, b = blockIdx.z;
    const int tid = threadIdx.x;
    #pragma unroll
    for (int i = 0; i < 16; i++) {
        int idx = tid + i * 256;
        int sl = idx >> 6, el = idx & 63;
        ts[sl][el] = x[((size_t)b * Sv + s0 + sl) * Ev + e0 + el];
    }
    __syncthreads();
    #pragma unroll
    for (int i = 0; i < 8; i++) {
        int item = tid + i * 256;
        int el = item >> 5, sp = item & 31;
        float v0 = ts[2 * sp][el], v1 = ts[2 * sp + 1][el];
        uint32_t h0, l0, h1, l1;
        split2(v0, h0, l0);
        split2(v1, h1, l1);
        size_t r = ((size_t)b * Ev + e0 + el) * LDHU + (s0 >> 1) + sp;
        xtH[r] = h0 | (h1 << 16);
        xtL[r] = l0 | (l1 << 16);
    }
    #pragma unroll
    for (int i = 0; i < 8; i++) {
        int item = tid + i * 256;
        int sl = item >> 5, pe = item & 31;
        float v0 = ts[sl][2 * pe], v1 = ts[sl][2 * pe + 1];
        uint32_t h0, l0, h1, l1;
        split2h(v0, h0, l0);
        split2h(v1, h1, l1);
        uint32_t* row = x2 + ((size_t)b * Sv + s0 + sl) * LDPU;
        int p = (e0 >> 1) + pe;
        row[p]       = h0 | (h1 << 16);
        row[384 + p] = l0 | (l1 << 16);
    }
}

// ---------------------------------------------------------------------------
// Merged weight packing (bf16 [hi|lo]): [Wq|Wk]^T and Wv rows.
// ---------------------------------------------------------------------------
__global__ void pack_w(const float* __restrict__ Wqkv,
                       uint32_t* __restrict__ wt1, uint32_t* __restrict__ wv2)
{
    int t = blockIdx.x * 256 + threadIdx.x;
    const int NW = 1536 * 384;
    if (t < NW) {
        int n = t / 384, kp = t % 384;
        float x0 = Wqkv[(size_t)(2 * kp) * 2304 + n];
        float x1 = Wqkv[(size_t)(2 * kp + 1) * 2304 + n];
        uint32_t h0, l0, h1, l1;
        split2(x0, h0, l0);
        split2(x1, h1, l1);
        uint32_t* o = wt1 + (size_t)n * LDPU + kp;
        o[0]   = h0 | (h1 << 16);
        o[384] = l0 | (l1 << 16);
    } else {
        int t2 = t - NW;
        if (t2 >= Ev * 384) return;
        int e = t2 / 384, c = t2 % 384;
        float x0 = Wqkv[(size_t)e * 2304 + 1536 + 2 * c];
        float x1 = Wqkv[(size_t)e * 2304 + 1536 + 2 * c + 1];
        uint32_t h0, l0, h1, l1;
        split2(x0, h0, l0);
        split2(x1, h1, l1);
        uint32_t* o = wv2 + (size_t)e * LDPU + c;
        o[0]   = h0 | (h1 << 16);
        o[384] = l0 | (l1 << 16);
    }
}

// ---------------------------------------------------------------------------
// Assemble C = R1(mirrored upper) + R2 + R2^T, pack bf16 [hi|lo] rows.
// Coalesced via 64x64 smem tiles. grid = (144, 16).
// ---------------------------------------------------------------------------
__global__ __launch_bounds__(256) void pack_ct(
    const float* __restrict__ R1, const float* __restrict__ R2,
    uint32_t* __restrict__ out)
{
    __shared__ float T2s[64][65];
    __shared__ float T1s[64][65];
    const int tm = blockIdx.x / 12, tn = blockIdx.x % 12;
    const int b = blockIdx.y;
    const int tid = threadIdx.x;
    const float* R1b = R1 + (size_t)b * Ev * Ev;
    const float* R2b = R2 + (size_t)b * Ev * Ev;
    uint32_t* ob = out + (size_t)b * Ev * LDPU;
    const bool r1dir = (tm >> 1) <= (tn >> 1);

    for (int idx = tid; idx < 64 * 64; idx += 256) {
        int r = idx >> 6, c = idx & 63;
        T2s[r][c] = R2b[(size_t)(tn * 64 + r) * Ev + tm * 64 + c];
    }
    if (!r1dir) {
        for (int idx = tid; idx < 64 * 64; idx += 256) {
            int r = idx >> 6, c = idx & 63;
            T1s[r][c] = R1b[(size_t)(tn * 64 + r) * Ev + tm * 64 + c];
        }
    }
    __syncthreads();

    for (int idx = tid; idx < 64 * 32; idx += 256) {
        int r = idx >> 5, p = idx & 31;
        int e1 = tm * 64 + r;
        int e2 = tn * 64 + 2 * p;
        float d0 = R2b[(size_t)e1 * Ev + e2];
        float d1 = R2b[(size_t)e1 * Ev + e2 + 1];
        float r10 = r1dir ? R1b[(size_t)e1 * Ev + e2]     : T1s[2 * p][r];
        float r11 = r1dir ? R1b[(size_t)e1 * Ev + e2 + 1] : T1s[2 * p + 1][r];
        float v0 = r10 + d0 + T2s[2 * p][r];
        float v1 = r11 + d1 + T2s[2 * p + 1][r];
        uint32_t h0, l0, h1, l1;
        split2(v0, h0, l0);
        split2(v1, h1, l1);
        uint32_t* o = ob + (size_t)e1 * LDPU + tn * 32 + p;
        o[0]   = h0 | (h1 << 16);
        o[384] = l0 | (l1 << 16);
    }
}

// ---------------------------------------------------------------------------
// Fused G + norms + softmax + fold. One block per (b,h).
// ---------------------------------------------------------------------------
#define CH2 48
__global__ __launch_bounds__(256) void k_gsfold(
    const float* __restrict__ Wqkv, const float* __restrict__ V2,
    const float* __restrict__ temp, const float* __restrict__ Wp,
    uint32_t* __restrict__ Pt2)
{
    __shared__ float smA[4][Dv][CH2 + 1];
    __shared__ float nr[96];
    float (*Wqs)[CH2 + 1] = smA[0];
    float (*Wks)[CH2 + 1] = smA[1];
    float (*Tqs)[CH2 + 1] = smA[2];
    float (*Us)[CH2 + 1]  = smA[3];
    float (*Gs)[CH2 + 1]  = smA[0];
    float* Ws = &smA[1][0][0];

    const int bh = blockIdx.x;
    const int b = bh >> 4, h = bh & 15;
    const int tid = threadIdx.x;
    const int tx = tid & 15, ty = tid >> 4;

    float acc[3][3];
    #pragma unroll
    for (int r = 0; r < 3; r++)
        #pragma unroll
        for (int c = 0; c < 3; c++) acc[r][c] = 0.f;
    float na = 0.f;

    for (int e0 = 0; e0 < Ev; e0 += CH2) {
        for (int idx = tid; idx < Dv * CH2; idx += 256) {
            int i = idx % Dv, el = idx / Dv;
            int e = e0 + el;
            const float* wrow = Wqkv + (size_t)e * 2304 + h * Dv;
            const float* vrow = V2 + ((size_t)b * Ev + e) * 1536 + h * Dv;
            Wqs[i][el] = wrow[i];
            Wks[i][el] = wrow[768 + i];
            Tqs[i][el] = vrow[i];
            Us[i][el]  = vrow[768 + i];
        }
        __syncthreads();
        #pragma unroll 4
        for (int el = 0; el < CH2; el++) {
            float qv[3], uv[3];
            #pragma unroll
            for (int r = 0; r < 3; r++) qv[r] = Wqs[3 * ty + r][el];
            #pragma unroll
            for (int c = 0; c < 3; c++) uv[c] = Us[3 * tx + c][el];
            #pragma unroll
            for (int r = 0; r < 3; r++)
                #pragma unroll
                for (int c = 0; c < 3; c++)
                    acc[r][c] = fmaf(qv[r], uv[c], acc[r][c]);
        }
        if (tid < 2 * Dv) {
            float a = 0.f;
            if (tid < Dv) {
                #pragma unroll 8
                for (int el = 0; el < CH2; el++)
                    a = fmaf(Wqs[tid][el], Tqs[tid][el], a);
            } else {
                int j = tid - Dv;
                #pragma unroll 8
                for (int el = 0; el < CH2; el++)
                    a = fmaf(Wks[j][el], Us[j][el], a);
            }
            na += a;
        }
        __syncthreads();
    }
    #pragma unroll
    for (int r = 0; r < 3; r++)
        #pragma unroll
        for (int c = 0; c < 3; c++)
            Gs[3 * ty + r][3 * tx + c] = acc[r][c];
    if (tid < 96) nr[tid] = fmaxf(sqrtf(na), 1e-12f);
    __syncthreads();

    const float T = temp[h];
    const int warp = tid >> 5, lane = tid & 31;
    for (int i = warp; i < Dv; i += 8) {
        float inq = T / nr[i];
        int j0 = lane, j1 = lane + 32;
        float v0 = Gs[i][j0] * inq / nr[Dv + j0];
        float v1 = (j1 < Dv) ? Gs[i][j1] * inq / nr[Dv + j1] : -INFINITY;
        float m = fmaxf(v0, v1);
        #pragma unroll
        for (int o = 16; o; o >>= 1) m = fmaxf(m, __shfl_xor_sync(~0u, m, o));
        float e0 = expf(v0 - m);
        float e1 = (j1 < Dv) ? expf(v1 - m) : 0.f;
        float ss = e0 + e1;
        #pragma unroll
        for (int o = 16; o; o >>= 1) ss += __shfl_xor_sync(~0u, ss, o);
        float inv = 1.f / ss;
        Gs[i][j0] = e0 * inv;
        if (j1 < Dv) Gs[i][j1] = e1 * inv;
    }
    __syncthreads();

    const int ftx = tid & 127;
    const int ftz = tid >> 7;
    uint32_t* Pb = Pt2 + (size_t)b * Ev * LDPU;
    for (int nb = 0; nb < 6; nb++) {
        for (int idx = tid; idx < Dv * 128; idx += 256) {
            int i = idx >> 7, c = idx & 127;
            Ws[i * 128 + c] = Wp[(size_t)(h * Dv + i) * Ev + nb * 128 + c];
        }
        __syncthreads();
        float fa[24];
        #pragma unroll
        for (int j = 0; j < 24; j++) fa[j] = 0.f;
        #pragma unroll 4
        for (int i = 0; i < Dv; i++) {
            float a = Ws[i * 128 + ftx];
            #pragma unroll
            for (int j = 0; j < 24; j++)
                fa[j] = fmaf(Gs[i][ftz * 24 + j], a, fa[j]);
        }
        int n = nb * 128 + ftx;
        uint32_t* ob = Pb + (size_t)n * LDPU;
        #pragma unroll
        for (int t = 0; t < 12; t++) {
            uint32_t h0, l0, h1, l1;
            split2(fa[2 * t], h0, l0);
            split2(fa[2 * t + 1], h1, l1);
            int p = h * 24 + ftz * 12 + t;
            ob[p]       = h0 | (h1 << 16);
            ob[384 + p] = l0 | (l1 << 16);
        }
        __syncthreads();
    }
}

// ---------------------------------------------------------------------------
// Launch
// ---------------------------------------------------------------------------
extern "C" void kernel_launch(void* const* d_in, const int* in_sizes, int n_in,
                              void* d_out, int out_size)
{
    const float* x      = (const float*)d_in[0];
    const float* W_qkv  = (const float*)d_in[1];
    const float* W_proj = (const float*)d_in[2];
    const float* b_proj = (const float*)d_in[3];
    const float* temp   = (const float*)d_in[4];
    float* outp = (float*)d_out;

    uint32_t *x2, *xtH, *xtL, *Cp, *wt1, *wv2, *Pt2, *wbT;
    float *R1, *R2, *V2;
    cudaGetSymbolAddress((void**)&x2, g_x2);
    cudaGetSymbolAddress((void**)&xtH, g_xtH);
    cudaGetSymbolAddress((void**)&xtL, g_xtL);
    cudaGetSymbolAddress((void**)&Cp, g_Cp);
    cudaGetSymbolAddress((void**)&wt1, g_wt1);
    cudaGetSymbolAddress((void**)&wv2, g_wv2);
    cudaGetSymbolAddress((void**)&Pt2, g_Pt2);
    cudaGetSymbolAddress((void**)&wbT, g_wbT);
    cudaGetSymbolAddress((void**)&R1, g_R1);
    cudaGetSymbolAddress((void**)&R2, g_R2);
    cudaGetSymbolAddress((void**)&V2, g_V2);

    cudaFuncSetAttribute(gemm_mma<false>,
                         cudaFuncAttributeMaxDynamicSharedMemorySize, GEMM_SMEM);
    cudaFuncSetAttribute(gemm_mma<true>,
                         cudaFuncAttributeMaxDynamicSharedMemorySize, GEMM_SMEM);

    // packing
    {
        dim3 grid(12, 49, 16);
        pack_x<<<grid, 256>>>(x, x2, xtH, xtL);
    }
    pack_w<<<((1536 + 768) * 384) / 256, 256>>>(W_qkv, wt1, wv2);

    // merged: R1 = H^T H (triangular, 21 tiles) + R2 = H^T L (36 tiles)
    {
        dim3 grid(21 + 36, 16);
        gemm_mma<false><<<grid, 256, GEMM_SMEM>>>(
            (const char*)xtH, (const char*)xtH, R1, nullptr, Ev, 6,
            (size_t)Ev * LDH, (size_t)Ev * LDH, (size_t)Ev * Ev,
            1 << 30, LDH, 49, 21, 0, (const char*)xtL, R2, 0);
    }
    // C = R1 + R2 + R2^T, packed bf16 [hi|lo]
    {
        dim3 grid(144, 16);
        pack_ct<<<grid, 256>>>(R1, R2, Cp);
    }
    // V2 = C @ [Wq|Wk]  (bf16 3-term)
    {
        dim3 grid(6 * 12, 16);
        gemm_mma<false><<<grid, 256, GEMM_SMEM>>>(
            (const char*)Cp, (const char*)wt1, V2, nullptr, 1536, 12,
            (size_t)Ev * LDP, 0, (size_t)Ev * 1536, 1 << 30, LDP, 36, 0, 1,
            nullptr, nullptr, 0);
    }
    // G + norms + softmax + fold (fused)
    k_gsfold<<<256, 256>>>(W_qkv, V2, temp, W_proj, Pt2);

    // WbT[n,e] = sum_m Pt[n,m] Wv[e,m] — bf16 3-term compute, fp16 packC out
    {
        dim3 grid(36, 16);
        gemm_mma<false><<<grid, 256, GEMM_SMEM>>>(
            (const char*)Pt2, (const char*)wv2, (float*)wbT, nullptr, Ev, 6,
            (size_t)Ev * LDP, 0, (size_t)Ev * LDPU, 1 << 30, LDP, 36, 0, 1,
            nullptr, nullptr, 2);
    }
    // final: out_b = X_b @ W_b + b_proj  (fp16 2-term, 24 chunks)
    {
        dim3 grid(25 * 6, 16);
        gemm_mma<true><<<grid, 256, GEMM_SMEM>>>(
            (const char*)x2, (const char*)wbT, outp, b_proj, Ev, 6,
            (size_t)Sv * LDP, (size_t)Ev * LDP, (size_t)Sv * Ev,
            Sv, LDP, 24, 0, 2, nullptr, nullptr, 0);
    }
}

// round 16
// speedup vs baseline: 1.3886x; 1.0995x over previous
#include <cuda_runtime.h>
#include <cuda_bf16.h>
#include <cuda_fp16.h>
#include <math.h>
#include <stdint.h>

// ---------------- problem constants ----------------
#define Bv 16
#define Sv 3136
#define Ev 768
#define Hv 16
#define Dv 48
#define NTOK (Bv * Sv)      // 50176
#define LDP 3072            // bytes per packed row: [hi(768)|lo(768)]
#define LDPU 768            // u32 per packed row
#define LDH 6272            // bytes per plain-bf16 row, K=3136
#define LDHU 1568           // u32 per plain row
#define NSTG 3
#define STG_BYTES 32768
#define GEMM_SMEM (NSTG * STG_BYTES)   // 98304

// ---------------- scratch (device globals) ----------------
__device__ uint32_t g_x2[(size_t)(NTOK + 128) * LDPU]; // packed x rows (fp16 hi|lo)
__device__ uint32_t g_xtH[(size_t)Bv * Ev * LDHU];     // X^T hi, plain bf16
__device__ uint32_t g_xtL[(size_t)Bv * Ev * LDHU];     // X^T lo, plain bf16
__device__ float    g_R1[(size_t)Bv * Ev * Ev];        // H^T H (upper tiles)
__device__ float    g_R2[(size_t)Bv * Ev * Ev];        // H^T L (full)
__device__ uint32_t g_Cp[(size_t)Bv * Ev * LDPU];      // C packed fp16 [hi|lo]
__device__ float    g_V2[(size_t)Bv * Ev * 1536];      // C @ [Wq|Wk]
__device__ uint32_t g_wt1[(size_t)1536 * LDPU];        // [Wq|Wk]^T packed fp16
__device__ uint32_t g_wv2[(size_t)Ev * LDPU];          // Wv rows packed fp16
__device__ uint32_t g_Pt2[(size_t)Bv * Ev * LDPU];     // P_b^T packed fp16
__device__ uint32_t g_wbT[(size_t)Bv * Ev * LDPU];     // W_b^T packed fp16

// ---------------- helpers ----------------
__device__ __forceinline__ uint32_t s2u(const void* p) {
    uint32_t a;
    asm("{ .reg .u64 t; cvta.to.shared.u64 t, %1; cvt.u32.u64 %0, t; }"
        : "=r"(a) : "l"(p));
    return a;
}
#define SWZ(o) ((o) ^ (((o) >> 3) & 0x70))

__device__ __forceinline__ void cpasync16(uint32_t s, const void* g) {
    asm volatile("cp.async.cg.shared.global [%0], [%1], 16;\n" :: "r"(s), "l"(g));
}
__device__ __forceinline__ void cp_commit() {
    asm volatile("cp.async.commit_group;\n");
}
template <int N> __device__ __forceinline__ void cp_wait() {
    asm volatile("cp.async.wait_group %0;\n" :: "n"(N));
}
__device__ __forceinline__ void ldm4(uint32_t& r0, uint32_t& r1, uint32_t& r2,
                                     uint32_t& r3, uint32_t a) {
    asm volatile("ldmatrix.sync.aligned.m8n8.x4.shared.b16 {%0,%1,%2,%3}, [%4];"
                 : "=r"(r0), "=r"(r1), "=r"(r2), "=r"(r3) : "r"(a));
}
template <bool F16>
__device__ __forceinline__ void mma16816(float* d, const uint32_t* a,
                                         const uint32_t* b) {
    if constexpr (F16) {
        asm volatile(
            "mma.sync.aligned.m16n8k16.row.col.f32.f16.f16.f32 "
            "{%0,%1,%2,%3}, {%4,%5,%6,%7}, {%8,%9}, {%0,%1,%2,%3};"
            : "+f"(d[0]), "+f"(d[1]), "+f"(d[2]), "+f"(d[3])
            : "r"(a[0]), "r"(a[1]), "r"(a[2]), "r"(a[3]), "r"(b[0]), "r"(b[1]));
    } else {
        asm volatile(
            "mma.sync.aligned.m16n8k16.row.col.f32.bf16.bf16.f32 "
            "{%0,%1,%2,%3}, {%4,%5,%6,%7}, {%8,%9}, {%0,%1,%2,%3};"
            : "+f"(d[0]), "+f"(d[1]), "+f"(d[2]), "+f"(d[3])
            : "r"(a[0]), "r"(a[1]), "r"(a[2]), "r"(a[3]), "r"(b[0]), "r"(b[1]));
    }
}
__device__ __forceinline__ void split2(float x, uint32_t& h, uint32_t& l) {
    __nv_bfloat16 hb = __float2bfloat16(x);
    float rem = x - __bfloat162float(hb);
    __nv_bfloat16 lb = __float2bfloat16(rem);
    h = (uint32_t)__bfloat16_as_ushort(hb);
    l = (uint32_t)__bfloat16_as_ushort(lb);
}
__device__ __forceinline__ void split2h(float x, uint32_t& h, uint32_t& l) {
    __half hb = __float2half(x);
    float rem = x - __half2float(hb);
    __half lb = __float2half(rem);
    h = (uint32_t)__half_as_ushort(hb);
    l = (uint32_t)__half_as_ushort(lb);
}

// ---------------------------------------------------------------------------
// mma.sync GEMM (proven config), templated on element type (bf16/fp16).
//  tri>0  : merged launch (triangular HtH tiles then rectangular HtL tiles).
//  tripK=1: 36 chunks over [hi|lo]: A (c<12?c:c-12), B (c<24?c:c-24).
//  tripK=2: 24 chunks: A (c<12?c:c-12), B (c) -> hi*hi, hi*lo (2-term).
//  packC=1: epilogue writes bf16 [hi|lo] rows; packC=2: fp16 [hi|lo] rows.
// ---------------------------------------------------------------------------
template <bool F16>
__global__ __launch_bounds__(256, 2) void gemm_mma(
    const char* __restrict__ A, const char* __restrict__ B,
    float* __restrict__ C, const float* __restrict__ bias, int N, int NT,
    size_t aStride, size_t bStride, size_t cStride, int Mrows,
    int kRowBytes, int nkch, int tri, int tripK,
    const char* __restrict__ Balt, float* __restrict__ Calt, int packC)
{
    extern __shared__ char sm[];
    const int tid  = threadIdx.x;
    const int wid  = tid >> 5, lane = tid & 31;
    const int wm   = wid & 3;
    const int wn   = wid >> 2;
    const int bat  = blockIdx.y;
    int bm, bn;
    const char* Bsel = B;
    float* Csel = C;
    if (tri > 0) {
        if ((int)blockIdx.x < tri) {
            int t = blockIdx.x, r = 0, rl = 6;
            while (t >= rl) { t -= rl; rl--; r++; }
            bm = r; bn = r + t;
        } else {
            int t = blockIdx.x - tri;
            bm = t / 6; bn = t % 6;
            Bsel = Balt; Csel = Calt;
        }
    } else {
        bm = blockIdx.x / NT; bn = blockIdx.x % NT;
    }
    const uint32_t smb = s2u(sm);

    const char* Ab = A + (size_t)bat * aStride + (size_t)bm * 128 * kRowBytes;
    const char* Bb = Bsel + (size_t)bat * bStride + (size_t)bn * 128 * kRowBytes;

    const int ldr = tid >> 1;
    const int ldc = (tid & 1) * 64;

    auto loadch = [&](int sp, int ck) {
        uint32_t sa = smb + sp * STG_BYTES;
        uint32_t sb = sa + 16384;
        int ca = ck, cb = ck;
        if (tripK == 1) {
            ca = (ck < 12) ? ck : ck - 12;
            cb = (ck < 24) ? ck : ck - 24;
        } else if (tripK == 2) {
            ca = (ck < 12) ? ck : ck - 12;
            cb = ck;
        }
        const char* a0 = Ab + ca * 128;
        const char* b0 = Bb + cb * 128;
        #pragma unroll
        for (int i = 0; i < 4; i++) {
            int cbyte = ldc + i * 16;
            cpasync16(sa + SWZ(ldr * 128 + cbyte),
                      a0 + (size_t)ldr * kRowBytes + cbyte);
            cpasync16(sb + SWZ(ldr * 128 + cbyte),
                      b0 + (size_t)ldr * kRowBytes + cbyte);
        }
        cp_commit();
    };

    float acc[2][8][4];
    #pragma unroll
    for (int m = 0; m < 2; m++)
        #pragma unroll
        for (int n = 0; n < 8; n++)
            #pragma unroll
            for (int p = 0; p < 4; p++) acc[m][n][p] = 0.f;

    loadch(0, 0);
    loadch(1, 1);

    const int a_row = (lane & 7) + ((lane >> 3) & 1) * 8;
    const int a_cb  = (lane >> 4) * 16;
    const int b_row = (lane & 7) + (lane >> 4) * 8;
    const int b_cb  = ((lane >> 3) & 1) * 16;

    uint32_t af[2][2][4], bf[2][8][2];

    auto ldfrag = [&](uint32_t sa, uint32_t sb, int ks, int buf) {
        #pragma unroll
        for (int mb = 0; mb < 2; mb++) {
            int r = wm * 32 + mb * 16 + a_row;
            ldm4(af[buf][mb][0], af[buf][mb][1], af[buf][mb][2], af[buf][mb][3],
                 sa + SWZ(r * 128 + ks * 32 + a_cb));
        }
        #pragma unroll
        for (int nb2 = 0; nb2 < 4; nb2++) {
            int r = wn * 64 + nb2 * 16 + b_row;
            ldm4(bf[buf][2 * nb2][0], bf[buf][2 * nb2][1],
                 bf[buf][2 * nb2 + 1][0], bf[buf][2 * nb2 + 1][1],
                 sb + SWZ(r * 128 + ks * 32 + b_cb));
        }
    };

    for (int k = 0; k < nkch; k++) {
        cp_wait<1>();
        __syncthreads();

        int kp = k + 2;
        if (kp < nkch) loadch(kp % NSTG, kp);
        else cp_commit();

        uint32_t sa = smb + (k % NSTG) * STG_BYTES;
        uint32_t sb = sa + 16384;

        ldfrag(sa, sb, 0, 0);
        #pragma unroll
        for (int ks = 0; ks < 4; ks++) {
            int c = ks & 1;
            if (ks < 3) ldfrag(sa, sb, ks + 1, c ^ 1);
            #pragma unroll
            for (int mb = 0; mb < 2; mb++)
                #pragma unroll
                for (int nb = 0; nb < 8; nb++)
                    mma16816<F16>(acc[mb][nb], af[c][mb], bf[c][nb]);
        }
    }

    const int er = lane >> 2;
    const int ec = (lane & 3) * 2;
    const int rbase = bm * 128 + wm * 32;

    if (packC) {
        uint32_t* Cpk = (uint32_t*)Csel + (size_t)bat * cStride;
        #pragma unroll
        for (int mb = 0; mb < 2; mb++) {
            int r0 = rbase + mb * 16 + er;
            #pragma unroll
            for (int nb = 0; nb < 8; nb++) {
                int col = bn * 128 + wn * 64 + nb * 8 + ec;   // even
                uint32_t h0, l0, h1, l1;
                if (packC == 2) { split2h(acc[mb][nb][0], h0, l0);
                                  split2h(acc[mb][nb][1], h1, l1); }
                else            { split2(acc[mb][nb][0], h0, l0);
                                  split2(acc[mb][nb][1], h1, l1); }
                uint32_t* o = Cpk + (size_t)r0 * LDPU + (col >> 1);
                o[0]   = h0 | (h1 << 16);
                o[384] = l0 | (l1 << 16);
                if (packC == 2) { split2h(acc[mb][nb][2], h0, l0);
                                  split2h(acc[mb][nb][3], h1, l1); }
                else            { split2(acc[mb][nb][2], h0, l0);
                                  split2(acc[mb][nb][3], h1, l1); }
                uint32_t* o2 = Cpk + (size_t)(r0 + 8) * LDPU + (col >> 1);
                o2[0]   = h0 | (h1 << 16);
                o2[384] = l0 | (l1 << 16);
            }
        }
        return;
    }

    float* Cb = Csel + (size_t)bat * cStride
                + (size_t)rbase * N + (size_t)bn * 128 + wn * 64;
    float bvs[8][2];
    #pragma unroll
    for (int nb = 0; nb < 8; nb++) {
        if (bias) {
            const float* bp = bias + (size_t)bn * 128 + wn * 64 + nb * 8 + ec;
            bvs[nb][0] = bp[0]; bvs[nb][1] = bp[1];
        } else { bvs[nb][0] = 0.f; bvs[nb][1] = 0.f; }
    }
    #pragma unroll
    for (int mb = 0; mb < 2; mb++) {
        int r0 = rbase + mb * 16 + er;
        bool w0 = r0 < Mrows, w1 = (r0 + 8) < Mrows;
        #pragma unroll
        for (int nb = 0; nb < 8; nb++) {
            int col = nb * 8 + ec;
            float2 v0 = {acc[mb][nb][0] + bvs[nb][0], acc[mb][nb][1] + bvs[nb][1]};
            float2 v1 = {acc[mb][nb][2] + bvs[nb][0], acc[mb][nb][3] + bvs[nb][1]};
            if (w0) *(float2*)(Cb + (size_t)(mb * 16 + er) * N + col) = v0;
            if (w1) *(float2*)(Cb + (size_t)(mb * 16 + er + 8) * N + col) = v1;
        }
    }
}

// ---------------------------------------------------------------------------
// Fused X packing: x2 = fp16 [hi|lo] rows; xtH/xtL = transposed plain bf16.
// grid = (12 e-tiles, 49 s-tiles, 16 b).
// ---------------------------------------------------------------------------
__global__ __launch_bounds__(256) void pack_x(
    const float* __restrict__ x, uint32_t* __restrict__ x2,
    uint32_t* __restrict__ xtH, uint32_t* __restrict__ xtL)
{
    __shared__ float ts[64][65];
    const int e0 = blockIdx.x * 64, s0 = blockIdx.y * 64, b = blockIdx.z;
    const int tid = threadIdx.x;
    #pragma unroll
    for (int i = 0; i < 16; i++) {
        int idx = tid + i * 256;
        int sl = idx >> 6, el = idx & 63;
        ts[sl][el] = x[((size_t)b * Sv + s0 + sl) * Ev + e0 + el];
    }
    __syncthreads();
    #pragma unroll
    for (int i = 0; i < 8; i++) {
        int item = tid + i * 256;
        int el = item >> 5, sp = item & 31;
        float v0 = ts[2 * sp][el], v1 = ts[2 * sp + 1][el];
        uint32_t h0, l0, h1, l1;
        split2(v0, h0, l0);
        split2(v1, h1, l1);
        size_t r = ((size_t)b * Ev + e0 + el) * LDHU + (s0 >> 1) + sp;
        xtH[r] = h0 | (h1 << 16);
        xtL[r] = l0 | (l1 << 16);
    }
    #pragma unroll
    for (int i = 0; i < 8; i++) {
        int item = tid + i * 256;
        int sl = item >> 5, pe = item & 31;
        float v0 = ts[sl][2 * pe], v1 = ts[sl][2 * pe + 1];
        uint32_t h0, l0, h1, l1;
        split2h(v0, h0, l0);
        split2h(v1, h1, l1);
        uint32_t* row = x2 + ((size_t)b * Sv + s0 + sl) * LDPU;
        int p = (e0 >> 1) + pe;
        row[p]       = h0 | (h1 << 16);
        row[384 + p] = l0 | (l1 << 16);
    }
}

// ---------------------------------------------------------------------------
// Merged weight packing (fp16 [hi|lo]): [Wq|Wk]^T and Wv rows.
// ---------------------------------------------------------------------------
__global__ void pack_w(const float* __restrict__ Wqkv,
                       uint32_t* __restrict__ wt1, uint32_t* __restrict__ wv2)
{
    int t = blockIdx.x * 256 + threadIdx.x;
    const int NW = 1536 * 384;
    if (t < NW) {
        int n = t / 384, kp = t % 384;
        float x0 = Wqkv[(size_t)(2 * kp) * 2304 + n];
        float x1 = Wqkv[(size_t)(2 * kp + 1) * 2304 + n];
        uint32_t h0, l0, h1, l1;
        split2h(x0, h0, l0);
        split2h(x1, h1, l1);
        uint32_t* o = wt1 + (size_t)n * LDPU + kp;
        o[0]   = h0 | (h1 << 16);
        o[384] = l0 | (l1 << 16);
    } else {
        int t2 = t - NW;
        if (t2 >= Ev * 384) return;
        int e = t2 / 384, c = t2 % 384;
        float x0 = Wqkv[(size_t)e * 2304 + 1536 + 2 * c];
        float x1 = Wqkv[(size_t)e * 2304 + 1536 + 2 * c + 1];
        uint32_t h0, l0, h1, l1;
        split2h(x0, h0, l0);
        split2h(x1, h1, l1);
        uint32_t* o = wv2 + (size_t)e * LDPU + c;
        o[0]   = h0 | (h1 << 16);
        o[384] = l0 | (l1 << 16);
    }
}

// ---------------------------------------------------------------------------
// Assemble C = R1(mirrored upper) + R2 + R2^T, pack fp16 [hi|lo] rows.
// Coalesced via 64x64 smem tiles. grid = (144, 16).
// ---------------------------------------------------------------------------
__global__ __launch_bounds__(256) void pack_ct(
    const float* __restrict__ R1, const float* __restrict__ R2,
    uint32_t* __restrict__ out)
{
    __shared__ float T2s[64][65];
    __shared__ float T1s[64][65];
    const int tm = blockIdx.x / 12, tn = blockIdx.x % 12;
    const int b = blockIdx.y;
    const int tid = threadIdx.x;
    const float* R1b = R1 + (size_t)b * Ev * Ev;
    const float* R2b = R2 + (size_t)b * Ev * Ev;
    uint32_t* ob = out + (size_t)b * Ev * LDPU;
    const bool r1dir = (tm >> 1) <= (tn >> 1);

    for (int idx = tid; idx < 64 * 64; idx += 256) {
        int r = idx >> 6, c = idx & 63;
        T2s[r][c] = R2b[(size_t)(tn * 64 + r) * Ev + tm * 64 + c];
    }
    if (!r1dir) {
        for (int idx = tid; idx < 64 * 64; idx += 256) {
            int r = idx >> 6, c = idx & 63;
            T1s[r][c] = R1b[(size_t)(tn * 64 + r) * Ev + tm * 64 + c];
        }
    }
    __syncthreads();

    for (int idx = tid; idx < 64 * 32; idx += 256) {
        int r = idx >> 5, p = idx & 31;
        int e1 = tm * 64 + r;
        int e2 = tn * 64 + 2 * p;
        float d0 = R2b[(size_t)e1 * Ev + e2];
        float d1 = R2b[(size_t)e1 * Ev + e2 + 1];
        float r10 = r1dir ? R1b[(size_t)e1 * Ev + e2]     : T1s[2 * p][r];
        float r11 = r1dir ? R1b[(size_t)e1 * Ev + e2 + 1] : T1s[2 * p + 1][r];
        float v0 = r10 + d0 + T2s[2 * p][r];
        float v1 = r11 + d1 + T2s[2 * p + 1][r];
        uint32_t h0, l0, h1, l1;
        split2h(v0, h0, l0);
        split2h(v1, h1, l1);
        uint32_t* o = ob + (size_t)e1 * LDPU + tn * 32 + p;
        o[0]   = h0 | (h1 << 16);
        o[384] = l0 | (l1 << 16);
    }
}

// ---------------------------------------------------------------------------
// Fused G + norms + softmax + fold. One block per (b,h).
// ---------------------------------------------------------------------------
#define CH2 48
__global__ __launch_bounds__(256) void k_gsfold(
    const float* __restrict__ Wqkv, const float* __restrict__ V2,
    const float* __restrict__ temp, const float* __restrict__ Wp,
    uint32_t* __restrict__ Pt2)
{
    __shared__ float smA[4][Dv][CH2 + 1];
    __shared__ float nr[96];
    float (*Wqs)[CH2 + 1] = smA[0];
    float (*Wks)[CH2 + 1] = smA[1];
    float (*Tqs)[CH2 + 1] = smA[2];
    float (*Us)[CH2 + 1]  = smA[3];
    float (*Gs)[CH2 + 1]  = smA[0];
    float* Ws = &smA[1][0][0];

    const int bh = blockIdx.x;
    const int b = bh >> 4, h = bh & 15;
    const int tid = threadIdx.x;
    const int tx = tid & 15, ty = tid >> 4;

    float acc[3][3];
    #pragma unroll
    for (int r = 0; r < 3; r++)
        #pragma unroll
        for (int c = 0; c < 3; c++) acc[r][c] = 0.f;
    float na = 0.f;

    for (int e0 = 0; e0 < Ev; e0 += CH2) {
        for (int idx = tid; idx < Dv * CH2; idx += 256) {
            int i = idx % Dv, el = idx / Dv;
            int e = e0 + el;
            const float* wrow = Wqkv + (size_t)e * 2304 + h * Dv;
            const float* vrow = V2 + ((size_t)b * Ev + e) * 1536 + h * Dv;
            Wqs[i][el] = wrow[i];
            Wks[i][el] = wrow[768 + i];
            Tqs[i][el] = vrow[i];
            Us[i][el]  = vrow[768 + i];
        }
        __syncthreads();
        #pragma unroll 4
        for (int el = 0; el < CH2; el++) {
            float qv[3], uv[3];
            #pragma unroll
            for (int r = 0; r < 3; r++) qv[r] = Wqs[3 * ty + r][el];
            #pragma unroll
            for (int c = 0; c < 3; c++) uv[c] = Us[3 * tx + c][el];
            #pragma unroll
            for (int r = 0; r < 3; r++)
                #pragma unroll
                for (int c = 0; c < 3; c++)
                    acc[r][c] = fmaf(qv[r], uv[c], acc[r][c]);
        }
        if (tid < 2 * Dv) {
            float a = 0.f;
            if (tid < Dv) {
                #pragma unroll 8
                for (int el = 0; el < CH2; el++)
                    a = fmaf(Wqs[tid][el], Tqs[tid][el], a);
            } else {
                int j = tid - Dv;
                #pragma unroll 8
                for (int el = 0; el < CH2; el++)
                    a = fmaf(Wks[j][el], Us[j][el], a);
            }
            na += a;
        }
        __syncthreads();
    }
    #pragma unroll
    for (int r = 0; r < 3; r++)
        #pragma unroll
        for (int c = 0; c < 3; c++)
            Gs[3 * ty + r][3 * tx + c] = acc[r][c];
    if (tid < 96) nr[tid] = fmaxf(sqrtf(na), 1e-12f);
    __syncthreads();

    const float T = temp[h];
    const int warp = tid >> 5, lane = tid & 31;
    for (int i = warp; i < Dv; i += 8) {
        float inq = T / nr[i];
        int j0 = lane, j1 = lane + 32;
        float v0 = Gs[i][j0] * inq / nr[Dv + j0];
        float v1 = (j1 < Dv) ? Gs[i][j1] * inq / nr[Dv + j1] : -INFINITY;
        float m = fmaxf(v0, v1);
        #pragma unroll
        for (int o = 16; o; o >>= 1) m = fmaxf(m, __shfl_xor_sync(~0u, m, o));
        float e0 = expf(v0 - m);
        float e1 = (j1 < Dv) ? expf(v1 - m) : 0.f;
        float ss = e0 + e1;
        #pragma unroll
        for (int o = 16; o; o >>= 1) ss += __shfl_xor_sync(~0u, ss, o);
        float inv = 1.f / ss;
        Gs[i][j0] = e0 * inv;
        if (j1 < Dv) Gs[i][j1] = e1 * inv;
    }
    __syncthreads();

    const int ftx = tid & 127;
    const int ftz = tid >> 7;
    uint32_t* Pb = Pt2 + (size_t)b * Ev * LDPU;
    for (int nb = 0; nb < 6; nb++) {
        for (int idx = tid; idx < Dv * 128; idx += 256) {
            int i = idx >> 7, c = idx & 127;
            Ws[i * 128 + c] = Wp[(size_t)(h * Dv + i) * Ev + nb * 128 + c];
        }
        __syncthreads();
        float fa[24];
        #pragma unroll
        for (int j = 0; j < 24; j++) fa[j] = 0.f;
        #pragma unroll 4
        for (int i = 0; i < Dv; i++) {
            float a = Ws[i * 128 + ftx];
            #pragma unroll
            for (int j = 0; j < 24; j++)
                fa[j] = fmaf(Gs[i][ftz * 24 + j], a, fa[j]);
        }
        int n = nb * 128 + ftx;
        uint32_t* ob = Pb + (size_t)n * LDPU;
        #pragma unroll
        for (int t = 0; t < 12; t++) {
            uint32_t h0, l0, h1, l1;
            split2h(fa[2 * t], h0, l0);
            split2h(fa[2 * t + 1], h1, l1);
            int p = h * 24 + ftz * 12 + t;
            ob[p]       = h0 | (h1 << 16);
            ob[384 + p] = l0 | (l1 << 16);
        }
        __syncthreads();
    }
}

// ---------------------------------------------------------------------------
// Launch
// ---------------------------------------------------------------------------
extern "C" void kernel_launch(void* const* d_in, const int* in_sizes, int n_in,
                              void* d_out, int out_size)
{
    const float* x      = (const float*)d_in[0];
    const float* W_qkv  = (const float*)d_in[1];
    const float* W_proj = (const float*)d_in[2];
    const float* b_proj = (const float*)d_in[3];
    const float* temp   = (const float*)d_in[4];
    float* outp = (float*)d_out;

    uint32_t *x2, *xtH, *xtL, *Cp, *wt1, *wv2, *Pt2, *wbT;
    float *R1, *R2, *V2;
    cudaGetSymbolAddress((void**)&x2, g_x2);
    cudaGetSymbolAddress((void**)&xtH, g_xtH);
    cudaGetSymbolAddress((void**)&xtL, g_xtL);
    cudaGetSymbolAddress((void**)&Cp, g_Cp);
    cudaGetSymbolAddress((void**)&wt1, g_wt1);
    cudaGetSymbolAddress((void**)&wv2, g_wv2);
    cudaGetSymbolAddress((void**)&Pt2, g_Pt2);
    cudaGetSymbolAddress((void**)&wbT, g_wbT);
    cudaGetSymbolAddress((void**)&R1, g_R1);
    cudaGetSymbolAddress((void**)&R2, g_R2);
    cudaGetSymbolAddress((void**)&V2, g_V2);

    cudaFuncSetAttribute(gemm_mma<false>,
                         cudaFuncAttributeMaxDynamicSharedMemorySize, GEMM_SMEM);
    cudaFuncSetAttribute(gemm_mma<true>,
                         cudaFuncAttributeMaxDynamicSharedMemorySize, GEMM_SMEM);

    // packing
    {
        dim3 grid(12, 49, 16);
        pack_x<<<grid, 256>>>(x, x2, xtH, xtL);
    }
    pack_w<<<((1536 + 768) * 384) / 256, 256>>>(W_qkv, wt1, wv2);

    // merged: R1 = H^T H (triangular, 21 tiles) + R2 = H^T L (36 tiles), bf16
    {
        dim3 grid(21 + 36, 16);
        gemm_mma<false><<<grid, 256, GEMM_SMEM>>>(
            (const char*)xtH, (const char*)xtH, R1, nullptr, Ev, 6,
            (size_t)Ev * LDH, (size_t)Ev * LDH, (size_t)Ev * Ev,
            1 << 30, LDH, 49, 21, 0, (const char*)xtL, R2, 0);
    }
    // C = R1 + R2 + R2^T, packed fp16 [hi|lo]
    {
        dim3 grid(144, 16);
        pack_ct<<<grid, 256>>>(R1, R2, Cp);
    }
    // V2 = C @ [Wq|Wk]  (fp16 2-term, 24 chunks)
    {
        dim3 grid(6 * 12, 16);
        gemm_mma<true><<<grid, 256, GEMM_SMEM>>>(
            (const char*)Cp, (const char*)wt1, V2, nullptr, 1536, 12,
            (size_t)Ev * LDP, 0, (size_t)Ev * 1536, 1 << 30, LDP, 24, 0, 2,
            nullptr, nullptr, 0);
    }
    // G + norms + softmax + fold (fused)
    k_gsfold<<<256, 256>>>(W_qkv, V2, temp, W_proj, Pt2);

    // WbT[n,e] = sum_m Pt[n,m] Wv[e,m]  (fp16 2-term, 24 chunks, fp16 packC)
    {
        dim3 grid(36, 16);
        gemm_mma<true><<<grid, 256, GEMM_SMEM>>>(
            (const char*)Pt2, (const char*)wv2, (float*)wbT, nullptr, Ev, 6,
            (size_t)Ev * LDP, 0, (size_t)Ev * LDPU, 1 << 30, LDP, 24, 0, 2,
            nullptr, nullptr, 2);
    }
    // final: out_b = X_b @ W_b + b_proj  (fp16 2-term, 24 chunks)
    {
        dim3 grid(25 * 6, 16);
        gemm_mma<true><<<grid, 256, GEMM_SMEM>>>(
            (const char*)x2, (const char*)wbT, outp, b_proj, Ev, 6,
            (size_t)Sv * LDP, (size_t)Ev * LDP, (size_t)Sv * Ev,
            Sv, LDP, 24, 0, 2, nullptr, nullptr, 0);
    }
}

// round 17
// speedup vs baseline: 1.8871x; 1.3590x over previous
#include <cuda_runtime.h>
#include <cuda_bf16.h>
#include <cuda_fp16.h>
#include <math.h>
#include <stdint.h>

// ---------------- problem constants ----------------
#define Bv 16
#define Sv 3136
#define Ev 768
#define Hv 16
#define Dv 48
#define NTOK (Bv * Sv)      // 50176
#define LDP 3072            // bytes per packed row: [hi(768)|lo(768)] (lo may be unused)
#define LDPU 768            // u32 per packed row
#define LDH 6272            // bytes per plain-bf16 row, K=3136
#define LDHU 1568           // u32 per plain row
#define NSTG 3
#define STG_BYTES 32768
#define GEMM_SMEM (NSTG * STG_BYTES)   // 98304

// ---------------- scratch (device globals) ----------------
__device__ uint32_t g_x2[(size_t)(NTOK + 128) * LDPU]; // packed x rows (fp16 hi)
__device__ uint32_t g_xtH[(size_t)Bv * Ev * LDHU];     // X^T hi, plain bf16
__device__ uint32_t g_xtL[(size_t)Bv * Ev * LDHU];     // X^T lo, plain bf16
__device__ float    g_R1[(size_t)Bv * Ev * Ev];        // H^T H (upper tiles)
__device__ float    g_R2[(size_t)Bv * Ev * Ev];        // H^T L (full)
__device__ uint32_t g_Cp[(size_t)Bv * Ev * LDPU];      // C packed fp16 hi
__device__ float    g_V2[(size_t)Bv * Ev * 1536];      // C @ [Wq|Wk]
__device__ uint32_t g_wt1[(size_t)1536 * LDPU];        // [Wq|Wk]^T packed fp16 hi
__device__ uint32_t g_wv2[(size_t)Ev * LDPU];          // Wv rows packed fp16 hi
__device__ uint32_t g_Pt2[(size_t)Bv * Ev * LDPU];     // P_b^T packed fp16 hi
__device__ uint32_t g_wbT[(size_t)Bv * Ev * LDPU];     // W_b^T packed fp16 hi

// ---------------- helpers ----------------
__device__ __forceinline__ uint32_t s2u(const void* p) {
    uint32_t a;
    asm("{ .reg .u64 t; cvta.to.shared.u64 t, %1; cvt.u32.u64 %0, t; }"
        : "=r"(a) : "l"(p));
    return a;
}
#define SWZ(o) ((o) ^ (((o) >> 3) & 0x70))

__device__ __forceinline__ void cpasync16(uint32_t s, const void* g) {
    asm volatile("cp.async.cg.shared.global [%0], [%1], 16;\n" :: "r"(s), "l"(g));
}
__device__ __forceinline__ void cp_commit() {
    asm volatile("cp.async.commit_group;\n");
}
template <int N> __device__ __forceinline__ void cp_wait() {
    asm volatile("cp.async.wait_group %0;\n" :: "n"(N));
}
__device__ __forceinline__ void ldm4(uint32_t& r0, uint32_t& r1, uint32_t& r2,
                                     uint32_t& r3, uint32_t a) {
    asm volatile("ldmatrix.sync.aligned.m8n8.x4.shared.b16 {%0,%1,%2,%3}, [%4];"
                 : "=r"(r0), "=r"(r1), "=r"(r2), "=r"(r3) : "r"(a));
}
template <bool F16>
__device__ __forceinline__ void mma16816(float* d, const uint32_t* a,
                                         const uint32_t* b) {
    if constexpr (F16) {
        asm volatile(
            "mma.sync.aligned.m16n8k16.row.col.f32.f16.f16.f32 "
            "{%0,%1,%2,%3}, {%4,%5,%6,%7}, {%8,%9}, {%0,%1,%2,%3};"
            : "+f"(d[0]), "+f"(d[1]), "+f"(d[2]), "+f"(d[3])
            : "r"(a[0]), "r"(a[1]), "r"(a[2]), "r"(a[3]), "r"(b[0]), "r"(b[1]));
    } else {
        asm volatile(
            "mma.sync.aligned.m16n8k16.row.col.f32.bf16.bf16.f32 "
            "{%0,%1,%2,%3}, {%4,%5,%6,%7}, {%8,%9}, {%0,%1,%2,%3};"
            : "+f"(d[0]), "+f"(d[1]), "+f"(d[2]), "+f"(d[3])
            : "r"(a[0]), "r"(a[1]), "r"(a[2]), "r"(a[3]), "r"(b[0]), "r"(b[1]));
    }
}
__device__ __forceinline__ void split2(float x, uint32_t& h, uint32_t& l) {
    __nv_bfloat16 hb = __float2bfloat16(x);
    float rem = x - __bfloat162float(hb);
    __nv_bfloat16 lb = __float2bfloat16(rem);
    h = (uint32_t)__bfloat16_as_ushort(hb);
    l = (uint32_t)__bfloat16_as_ushort(lb);
}
__device__ __forceinline__ uint32_t h2pack(float a, float b) {
    __half2 hv = __floats2half2_rn(a, b);
    return *(uint32_t*)&hv;
}

// ---------------------------------------------------------------------------
// mma.sync GEMM (proven config), templated on element type (bf16/fp16).
//  tri>0  : merged launch (triangular HtH tiles then rectangular HtL tiles).
//  tripK=0: plain chunk map (with nkch=12 reads hi halves only -> 1-term).
//  tripK=1: 36 chunks: A (c<12?c:c-12), B (c<24?c:c-24) -> 3-term.
//  tripK=2: 24 chunks: A (c<12?c:c-12), B (c) -> 2-term.
//  packC=2: epilogue writes fp16 hi rows into (uint32_t*)C.
// ---------------------------------------------------------------------------
template <bool F16>
__global__ __launch_bounds__(256, 2) void gemm_mma(
    const char* __restrict__ A, const char* __restrict__ B,
    float* __restrict__ C, const float* __restrict__ bias, int N, int NT,
    size_t aStride, size_t bStride, size_t cStride, int Mrows,
    int kRowBytes, int nkch, int tri, int tripK,
    const char* __restrict__ Balt, float* __restrict__ Calt, int packC)
{
    extern __shared__ char sm[];
    const int tid  = threadIdx.x;
    const int wid  = tid >> 5, lane = tid & 31;
    const int wm   = wid & 3;
    const int wn   = wid >> 2;
    const int bat  = blockIdx.y;
    int bm, bn;
    const char* Bsel = B;
    float* Csel = C;
    if (tri > 0) {
        if ((int)blockIdx.x < tri) {
            int t = blockIdx.x, r = 0, rl = 6;
            while (t >= rl) { t -= rl; rl--; r++; }
            bm = r; bn = r + t;
        } else {
            int t = blockIdx.x - tri;
            bm = t / 6; bn = t % 6;
            Bsel = Balt; Csel = Calt;
        }
    } else {
        bm = blockIdx.x / NT; bn = blockIdx.x % NT;
    }
    const uint32_t smb = s2u(sm);

    const char* Ab = A + (size_t)bat * aStride + (size_t)bm * 128 * kRowBytes;
    const char* Bb = Bsel + (size_t)bat * bStride + (size_t)bn * 128 * kRowBytes;

    const int ldr = tid >> 1;
    const int ldc = (tid & 1) * 64;

    auto loadch = [&](int sp, int ck) {
        uint32_t sa = smb + sp * STG_BYTES;
        uint32_t sb = sa + 16384;
        int ca = ck, cb = ck;
        if (tripK == 1) {
            ca = (ck < 12) ? ck : ck - 12;
            cb = (ck < 24) ? ck : ck - 24;
        } else if (tripK == 2) {
            ca = (ck < 12) ? ck : ck - 12;
            cb = ck;
        }
        const char* a0 = Ab + ca * 128;
        const char* b0 = Bb + cb * 128;
        #pragma unroll
        for (int i = 0; i < 4; i++) {
            int cbyte = ldc + i * 16;
            cpasync16(sa + SWZ(ldr * 128 + cbyte),
                      a0 + (size_t)ldr * kRowBytes + cbyte);
            cpasync16(sb + SWZ(ldr * 128 + cbyte),
                      b0 + (size_t)ldr * kRowBytes + cbyte);
        }
        cp_commit();
    };

    float acc[2][8][4];
    #pragma unroll
    for (int m = 0; m < 2; m++)
        #pragma unroll
        for (int n = 0; n < 8; n++)
            #pragma unroll
            for (int p = 0; p < 4; p++) acc[m][n][p] = 0.f;

    loadch(0, 0);
    loadch(1, 1);

    const int a_row = (lane & 7) + ((lane >> 3) & 1) * 8;
    const int a_cb  = (lane >> 4) * 16;
    const int b_row = (lane & 7) + (lane >> 4) * 8;
    const int b_cb  = ((lane >> 3) & 1) * 16;

    uint32_t af[2][2][4], bf[2][8][2];

    auto ldfrag = [&](uint32_t sa, uint32_t sb, int ks, int buf) {
        #pragma unroll
        for (int mb = 0; mb < 2; mb++) {
            int r = wm * 32 + mb * 16 + a_row;
            ldm4(af[buf][mb][0], af[buf][mb][1], af[buf][mb][2], af[buf][mb][3],
                 sa + SWZ(r * 128 + ks * 32 + a_cb));
        }
        #pragma unroll
        for (int nb2 = 0; nb2 < 4; nb2++) {
            int r = wn * 64 + nb2 * 16 + b_row;
            ldm4(bf[buf][2 * nb2][0], bf[buf][2 * nb2][1],
                 bf[buf][2 * nb2 + 1][0], bf[buf][2 * nb2 + 1][1],
                 sb + SWZ(r * 128 + ks * 32 + b_cb));
        }
    };

    for (int k = 0; k < nkch; k++) {
        cp_wait<1>();
        __syncthreads();

        int kp = k + 2;
        if (kp < nkch) loadch(kp % NSTG, kp);
        else cp_commit();

        uint32_t sa = smb + (k % NSTG) * STG_BYTES;
        uint32_t sb = sa + 16384;

        ldfrag(sa, sb, 0, 0);
        #pragma unroll
        for (int ks = 0; ks < 4; ks++) {
            int c = ks & 1;
            if (ks < 3) ldfrag(sa, sb, ks + 1, c ^ 1);
            #pragma unroll
            for (int mb = 0; mb < 2; mb++)
                #pragma unroll
                for (int nb = 0; nb < 8; nb++)
                    mma16816<F16>(acc[mb][nb], af[c][mb], bf[c][nb]);
        }
    }

    const int er = lane >> 2;
    const int ec = (lane & 3) * 2;
    const int rbase = bm * 128 + wm * 32;

    if (packC) {
        // fp16 hi-only rows (consumer is a 1-term fp16 GEMM)
        uint32_t* Cpk = (uint32_t*)Csel + (size_t)bat * cStride;
        #pragma unroll
        for (int mb = 0; mb < 2; mb++) {
            int r0 = rbase + mb * 16 + er;
            #pragma unroll
            for (int nb = 0; nb < 8; nb++) {
                int col = bn * 128 + wn * 64 + nb * 8 + ec;   // even
                Cpk[(size_t)r0 * LDPU + (col >> 1)] =
                    h2pack(acc[mb][nb][0], acc[mb][nb][1]);
                Cpk[(size_t)(r0 + 8) * LDPU + (col >> 1)] =
                    h2pack(acc[mb][nb][2], acc[mb][nb][3]);
            }
        }
        return;
    }

    float* Cb = Csel + (size_t)bat * cStride
                + (size_t)rbase * N + (size_t)bn * 128 + wn * 64;
    float bvs[8][2];
    #pragma unroll
    for (int nb = 0; nb < 8; nb++) {
        if (bias) {
            const float* bp = bias + (size_t)bn * 128 + wn * 64 + nb * 8 + ec;
            bvs[nb][0] = bp[0]; bvs[nb][1] = bp[1];
        } else { bvs[nb][0] = 0.f; bvs[nb][1] = 0.f; }
    }
    #pragma unroll
    for (int mb = 0; mb < 2; mb++) {
        int r0 = rbase + mb * 16 + er;
        bool w0 = r0 < Mrows, w1 = (r0 + 8) < Mrows;
        #pragma unroll
        for (int nb = 0; nb < 8; nb++) {
            int col = nb * 8 + ec;
            float2 v0 = {acc[mb][nb][0] + bvs[nb][0], acc[mb][nb][1] + bvs[nb][1]};
            float2 v1 = {acc[mb][nb][2] + bvs[nb][0], acc[mb][nb][3] + bvs[nb][1]};
            if (w0) *(float2*)(Cb + (size_t)(mb * 16 + er) * N + col) = v0;
            if (w1) *(float2*)(Cb + (size_t)(mb * 16 + er + 8) * N + col) = v1;
        }
    }
}

// ---------------------------------------------------------------------------
// Fused X packing: x2 = fp16 hi rows; xtH/xtL = transposed plain bf16 hi/lo.
// grid = (12 e-tiles, 49 s-tiles, 16 b).
// ---------------------------------------------------------------------------
__global__ __launch_bounds__(256) void pack_x(
    const float* __restrict__ x, uint32_t* __restrict__ x2,
    uint32_t* __restrict__ xtH, uint32_t* __restrict__ xtL)
{
    __shared__ float ts[64][65];
    const int e0 = blockIdx.x * 64, s0 = blockIdx.y * 64, b = blockIdx.z;
    const int tid = threadIdx.x;
    #pragma unroll
    for (int i = 0; i < 16; i++) {
        int idx = tid + i * 256;
        int sl = idx >> 6, el = idx & 63;
        ts[sl][el] = x[((size_t)b * Sv + s0 + sl) * Ev + e0 + el];
    }
    __syncthreads();
    #pragma unroll
    for (int i = 0; i < 8; i++) {
        int item = tid + i * 256;
        int el = item >> 5, sp = item & 31;
        float v0 = ts[2 * sp][el], v1 = ts[2 * sp + 1][el];
        uint32_t h0, l0, h1, l1;
        split2(v0, h0, l0);
        split2(v1, h1, l1);
        size_t r = ((size_t)b * Ev + e0 + el) * LDHU + (s0 >> 1) + sp;
        xtH[r] = h0 | (h1 << 16);
        xtL[r] = l0 | (l1 << 16);
    }
    #pragma unroll
    for (int i = 0; i < 8; i++) {
        int item = tid + i * 256;
        int sl = item >> 5, pe = item & 31;
        uint32_t* row = x2 + ((size_t)b * Sv + s0 + sl) * LDPU;
        row[(e0 >> 1) + pe] = h2pack(ts[sl][2 * pe], ts[sl][2 * pe + 1]);
    }
}

// ---------------------------------------------------------------------------
// Merged weight packing (fp16 hi): [Wq|Wk]^T and Wv rows.
// ---------------------------------------------------------------------------
__global__ void pack_w(const float* __restrict__ Wqkv,
                       uint32_t* __restrict__ wt1, uint32_t* __restrict__ wv2)
{
    int t = blockIdx.x * 256 + threadIdx.x;
    const int NW = 1536 * 384;
    if (t < NW) {
        int n = t / 384, kp = t % 384;
        wt1[(size_t)n * LDPU + kp] =
            h2pack(Wqkv[(size_t)(2 * kp) * 2304 + n],
                   Wqkv[(size_t)(2 * kp + 1) * 2304 + n]);
    } else {
        int t2 = t - NW;
        if (t2 >= Ev * 384) return;
        int e = t2 / 384, c = t2 % 384;
        wv2[(size_t)e * LDPU + c] =
            h2pack(Wqkv[(size_t)e * 2304 + 1536 + 2 * c],
                   Wqkv[(size_t)e * 2304 + 1536 + 2 * c + 1]);
    }
}

// ---------------------------------------------------------------------------
// Assemble C = R1(mirrored upper) + R2 + R2^T, pack fp16 hi rows.
// Coalesced via 64x64 smem tiles. grid = (144, 16).
// ---------------------------------------------------------------------------
__global__ __launch_bounds__(256) void pack_ct(
    const float* __restrict__ R1, const float* __restrict__ R2,
    uint32_t* __restrict__ out)
{
    __shared__ float T2s[64][65];
    __shared__ float T1s[64][65];
    const int tm = blockIdx.x / 12, tn = blockIdx.x % 12;
    const int b = blockIdx.y;
    const int tid = threadIdx.x;
    const float* R1b = R1 + (size_t)b * Ev * Ev;
    const float* R2b = R2 + (size_t)b * Ev * Ev;
    uint32_t* ob = out + (size_t)b * Ev * LDPU;
    const bool r1dir = (tm >> 1) <= (tn >> 1);

    for (int idx = tid; idx < 64 * 64; idx += 256) {
        int r = idx >> 6, c = idx & 63;
        T2s[r][c] = R2b[(size_t)(tn * 64 + r) * Ev + tm * 64 + c];
    }
    if (!r1dir) {
        for (int idx = tid; idx < 64 * 64; idx += 256) {
            int r = idx >> 6, c = idx & 63;
            T1s[r][c] = R1b[(size_t)(tn * 64 + r) * Ev + tm * 64 + c];
        }
    }
    __syncthreads();

    for (int idx = tid; idx < 64 * 32; idx += 256) {
        int r = idx >> 5, p = idx & 31;
        int e1 = tm * 64 + r;
        int e2 = tn * 64 + 2 * p;
        float d0 = R2b[(size_t)e1 * Ev + e2];
        float d1 = R2b[(size_t)e1 * Ev + e2 + 1];
        float r10 = r1dir ? R1b[(size_t)e1 * Ev + e2]     : T1s[2 * p][r];
        float r11 = r1dir ? R1b[(size_t)e1 * Ev + e2 + 1] : T1s[2 * p + 1][r];
        float v0 = r10 + d0 + T2s[2 * p][r];
        float v1 = r11 + d1 + T2s[2 * p + 1][r];
        ob[(size_t)e1 * LDPU + tn * 32 + p] = h2pack(v0, v1);
    }
}

// ---------------------------------------------------------------------------
// Fused G + norms + softmax + fold. One block per (b,h).
// ---------------------------------------------------------------------------
#define CH2 48
__global__ __launch_bounds__(256) void k_gsfold(
    const float* __restrict__ Wqkv, const float* __restrict__ V2,
    const float* __restrict__ temp, const float* __restrict__ Wp,
    uint32_t* __restrict__ Pt2)
{
    __shared__ float smA[4][Dv][CH2 + 1];
    __shared__ float nr[96];
    float (*Wqs)[CH2 + 1] = smA[0];
    float (*Wks)[CH2 + 1] = smA[1];
    float (*Tqs)[CH2 + 1] = smA[2];
    float (*Us)[CH2 + 1]  = smA[3];
    float (*Gs)[CH2 + 1]  = smA[0];
    float* Ws = &smA[1][0][0];

    const int bh = blockIdx.x;
    const int b = bh >> 4, h = bh & 15;
    const int tid = threadIdx.x;
    const int tx = tid & 15, ty = tid >> 4;

    float acc[3][3];
    #pragma unroll
    for (int r = 0; r < 3; r++)
        #pragma unroll
        for (int c = 0; c < 3; c++) acc[r][c] = 0.f;
    float na = 0.f;

    for (int e0 = 0; e0 < Ev; e0 += CH2) {
        for (int idx = tid; idx < Dv * CH2; idx += 256) {
            int i = idx % Dv, el = idx / Dv;
            int e = e0 + el;
            const float* wrow = Wqkv + (size_t)e * 2304 + h * Dv;
            const float* vrow = V2 + ((size_t)b * Ev + e) * 1536 + h * Dv;
            Wqs[i][el] = wrow[i];
            Wks[i][el] = wrow[768 + i];
            Tqs[i][el] = vrow[i];
            Us[i][el]  = vrow[768 + i];
        }
        __syncthreads();
        #pragma unroll 4
        for (int el = 0; el < CH2; el++) {
            float qv[3], uv[3];
            #pragma unroll
            for (int r = 0; r < 3; r++) qv[r] = Wqs[3 * ty + r][el];
            #pragma unroll
            for (int c = 0; c < 3; c++) uv[c] = Us[3 * tx + c][el];
            #pragma unroll
            for (int r = 0; r < 3; r++)
                #pragma unroll
                for (int c = 0; c < 3; c++)
                    acc[r][c] = fmaf(qv[r], uv[c], acc[r][c]);
        }
        if (tid < 2 * Dv) {
            float a = 0.f;
            if (tid < Dv) {
                #pragma unroll 8
                for (int el = 0; el < CH2; el++)
                    a = fmaf(Wqs[tid][el], Tqs[tid][el], a);
            } else {
                int j = tid - Dv;
                #pragma unroll 8
                for (int el = 0; el < CH2; el++)
                    a = fmaf(Wks[j][el], Us[j][el], a);
            }
            na += a;
        }
        __syncthreads();
    }
    #pragma unroll
    for (int r = 0; r < 3; r++)
        #pragma unroll
        for (int c = 0; c < 3; c++)
            Gs[3 * ty + r][3 * tx + c] = acc[r][c];
    if (tid < 96) nr[tid] = fmaxf(sqrtf(na), 1e-12f);
    __syncthreads();

    const float T = temp[h];
    const int warp = tid >> 5, lane = tid & 31;
    for (int i = warp; i < Dv; i += 8) {
        float inq = T / nr[i];
        int j0 = lane, j1 = lane + 32;
        float v0 = Gs[i][j0] * inq / nr[Dv + j0];
        float v1 = (j1 < Dv) ? Gs[i][j1] * inq / nr[Dv + j1] : -INFINITY;
        float m = fmaxf(v0, v1);
        #pragma unroll
        for (int o = 16; o; o >>= 1) m = fmaxf(m, __shfl_xor_sync(~0u, m, o));
        float e0 = expf(v0 - m);
        float e1 = (j1 < Dv) ? expf(v1 - m) : 0.f;
        float ss = e0 + e1;
        #pragma unroll
        for (int o = 16; o; o >>= 1) ss += __shfl_xor_sync(~0u, ss, o);
        float inv = 1.f / ss;
        Gs[i][j0] = e0 * inv;
        if (j1 < Dv) Gs[i][j1] = e1 * inv;
    }
    __syncthreads();

    const int ftx = tid & 127;
    const int ftz = tid >> 7;
    uint32_t* Pb = Pt2 + (size_t)b * Ev * LDPU;
    for (int nb = 0; nb < 6; nb++) {
        for (int idx = tid; idx < Dv * 128; idx += 256) {
            int i = idx >> 7, c = idx & 127;
            Ws[i * 128 + c] = Wp[(size_t)(h * Dv + i) * Ev + nb * 128 + c];
        }
        __syncthreads();
        float fa[24];
        #pragma unroll
        for (int j = 0; j < 24; j++) fa[j] = 0.f;
        #pragma unroll 4
        for (int i = 0; i < Dv; i++) {
            float a = Ws[i * 128 + ftx];
            #pragma unroll
            for (int j = 0; j < 24; j++)
                fa[j] = fmaf(Gs[i][ftz * 24 + j], a, fa[j]);
        }
        int n = nb * 128 + ftx;
        uint32_t* ob = Pb + (size_t)n * LDPU;
        #pragma unroll
        for (int t = 0; t < 12; t++)
            ob[h * 24 + ftz * 12 + t] = h2pack(fa[2 * t], fa[2 * t + 1]);
        __syncthreads();
    }
}

// ---------------------------------------------------------------------------
// Launch
// ---------------------------------------------------------------------------
extern "C" void kernel_launch(void* const* d_in, const int* in_sizes, int n_in,
                              void* d_out, int out_size)
{
    const float* x      = (const float*)d_in[0];
    const float* W_qkv  = (const float*)d_in[1];
    const float* W_proj = (const float*)d_in[2];
    const float* b_proj = (const float*)d_in[3];
    const float* temp   = (const float*)d_in[4];
    float* outp = (float*)d_out;

    uint32_t *x2, *xtH, *xtL, *Cp, *wt1, *wv2, *Pt2, *wbT;
    float *R1, *R2, *V2;
    cudaGetSymbolAddress((void**)&x2, g_x2);
    cudaGetSymbolAddress((void**)&xtH, g_xtH);
    cudaGetSymbolAddress((void**)&xtL, g_xtL);
    cudaGetSymbolAddress((void**)&Cp, g_Cp);
    cudaGetSymbolAddress((void**)&wt1, g_wt1);
    cudaGetSymbolAddress((void**)&wv2, g_wv2);
    cudaGetSymbolAddress((void**)&Pt2, g_Pt2);
    cudaGetSymbolAddress((void**)&wbT, g_wbT);
    cudaGetSymbolAddress((void**)&R1, g_R1);
    cudaGetSymbolAddress((void**)&R2, g_R2);
    cudaGetSymbolAddress((void**)&V2, g_V2);

    cudaFuncSetAttribute(gemm_mma<false>,
                         cudaFuncAttributeMaxDynamicSharedMemorySize, GEMM_SMEM);
    cudaFuncSetAttribute(gemm_mma<true>,
                         cudaFuncAttributeMaxDynamicSharedMemorySize, GEMM_SMEM);

    // packing
    {
        dim3 grid(12, 49, 16);
        pack_x<<<grid, 256>>>(x, x2, xtH, xtL);
    }
    pack_w<<<((1536 + 768) * 384) / 256, 256>>>(W_qkv, wt1, wv2);

    // merged: R1 = H^T H (triangular, 21 tiles) + R2 = H^T L (36 tiles), bf16
    {
        dim3 grid(21 + 36, 16);
        gemm_mma<false><<<grid, 256, GEMM_SMEM>>>(
            (const char*)xtH, (const char*)xtH, R1, nullptr, Ev, 6,
            (size_t)Ev * LDH, (size_t)Ev * LDH, (size_t)Ev * Ev,
            1 << 30, LDH, 49, 21, 0, (const char*)xtL, R2, 0);
    }
    // C = R1 + R2 + R2^T, packed fp16 hi
    {
        dim3 grid(144, 16);
        pack_ct<<<grid, 256>>>(R1, R2, Cp);
    }
    // V2 = C @ [Wq|Wk]  (fp16 1-term, 12 chunks)
    {
        dim3 grid(6 * 12, 16);
        gemm_mma<true><<<grid, 256, GEMM_SMEM>>>(
            (const char*)Cp, (const char*)wt1, V2, nullptr, 1536, 12,
            (size_t)Ev * LDP, 0, (size_t)Ev * 1536, 1 << 30, LDP, 12, 0, 0,
            nullptr, nullptr, 0);
    }
    // G + norms + softmax + fold (fused)
    k_gsfold<<<256, 256>>>(W_qkv, V2, temp, W_proj, Pt2);

    // WbT[n,e] = sum_m Pt[n,m] Wv[e,m]  (fp16 1-term, fp16 hi packC)
    {
        dim3 grid(36, 16);
        gemm_mma<true><<<grid, 256, GEMM_SMEM>>>(
            (const char*)Pt2, (const char*)wv2, (float*)wbT, nullptr, Ev, 6,
            (size_t)Ev * LDP, 0, (size_t)Ev * LDPU, 1 << 30, LDP, 12, 0, 0,
            nullptr, nullptr, 2);
    }
    // final: out_b = X_b @ W_b + b_proj  (fp16 1-term, 12 chunks)
    {
        dim3 grid(25 * 6, 16);
        gemm_mma<true><<<grid, 256, GEMM_SMEM>>>(
            (const char*)x2, (const char*)wbT, outp, b_proj, Ev, 6,
            (size_t)Sv * LDP, (size_t)Ev * LDP, (size_t)Sv * Ev,
            Sv, LDP, 12, 0, 0, nullptr, nullptr, 0);
    }
}